// round 1
// baseline (speedup 1.0000x reference)
#include <cuda_runtime.h>
#include <cuda_bf16.h>
#include <math.h>
#include <float.h>

// Problem constants
#define BB 2
#define LL 2048
#define DD 1024
#define HH 16
#define HD 64
#define TOPU 40
#define MM (BB*LL)          // 4096 rows
#define SCALE 0.125f        // 1/sqrt(64)

// ---------------- scratch (device globals; no allocation allowed) -------------
__device__ float g_qkv[3][MM*DD];        // projected q,k,v  (3 x 16MB)
__device__ float g_sp[BB*HH*LL];         // sparsity scores
__device__ int g_topk[BB*HH*TOPU];
__device__ unsigned g_selmask[BB*LL];    // per-row bitmask of heads that selected it
__device__ int g_selu[BB*LL*HH];         // u index per (row, head)
__device__ float g_ctx[BB*HH*TOPU*HD];   // attention outputs for top queries
__device__ float g_base[BB*DD];          // mean(V) per head, flattened [b][h*64+d]
__device__ float g_baseout[BB*DD];       // base_row @ Wo^T + bo

// ---------------- Projection GEMM: Y = X @ W^T + bias ----------------
// X: [M=4096, K=1024] row-major, W: [N=1024, K=1024] row-major, Y: [M, N]
__global__ __launch_bounds__(256) void sgemm_nt(const float* __restrict__ X,
                                                const float* __restrict__ W,
                                                const float* __restrict__ bias,
                                                int which) {
    __shared__ float As[8][128];
    __shared__ float Bs[8][128];
    float* __restrict__ Y = g_qkv[which];
    const int tid = threadIdx.x;
    const int bm = blockIdx.y * 128;
    const int bn = blockIdx.x * 128;
    const int lrow = tid >> 1;
    const int lcol = (tid & 1) << 2;
    const int tx = tid & 15;
    const int ty = tid >> 4;

    float acc[8][8];
#pragma unroll
    for (int i = 0; i < 8; ++i)
#pragma unroll
        for (int j = 0; j < 8; ++j) acc[i][j] = 0.f;

    const float* Xp = X + (size_t)(bm + lrow) * DD + lcol;
    const float* Wp = W + (size_t)(bn + lrow) * DD + lcol;

    for (int k0 = 0; k0 < DD; k0 += 8) {
        float4 xa = *(const float4*)(Xp + k0);
        float4 wa = *(const float4*)(Wp + k0);
        As[lcol + 0][lrow] = xa.x; As[lcol + 1][lrow] = xa.y;
        As[lcol + 2][lrow] = xa.z; As[lcol + 3][lrow] = xa.w;
        Bs[lcol + 0][lrow] = wa.x; Bs[lcol + 1][lrow] = wa.y;
        Bs[lcol + 2][lrow] = wa.z; Bs[lcol + 3][lrow] = wa.w;
        __syncthreads();
#pragma unroll
        for (int k = 0; k < 8; ++k) {
            float a[8], b[8];
            *(float4*)&a[0] = *(const float4*)&As[k][ty * 8];
            *(float4*)&a[4] = *(const float4*)&As[k][ty * 8 + 4];
            *(float4*)&b[0] = *(const float4*)&Bs[k][tx * 8];
            *(float4*)&b[4] = *(const float4*)&Bs[k][tx * 8 + 4];
#pragma unroll
            for (int i = 0; i < 8; ++i)
#pragma unroll
                for (int j = 0; j < 8; ++j) acc[i][j] += a[i] * b[j];
        }
        __syncthreads();
    }
    float bs[8];
#pragma unroll
    for (int j = 0; j < 8; ++j) bs[j] = bias[bn + tx * 8 + j];
#pragma unroll
    for (int i = 0; i < 8; ++i) {
        int m = bm + ty * 8 + i;
#pragma unroll
        for (int j = 0; j < 8; j += 4) {
            float4 o;
            o.x = acc[i][j + 0] + bs[j + 0];
            o.y = acc[i][j + 1] + bs[j + 1];
            o.z = acc[i][j + 2] + bs[j + 2];
            o.w = acc[i][j + 3] + bs[j + 3];
            *(float4*)(Y + (size_t)m * DD + bn + tx * 8 + j) = o;
        }
    }
}

// ---------------- Fused QK^T + sparsity reduction ----------------
// For each (b,h): sparsity[q] = scale*max_k(q.k) - scale*sum_k(q.k)/2048
// Never materializes scores. grid: (L/128, H, B), block 256.
__global__ __launch_bounds__(256) void sparsity_kernel() {
    const int b = blockIdx.z, h = blockIdx.y;
    const int q0 = blockIdx.x * 128;
    __shared__ float Qs[64][128];   // [d][q] 32KB
    __shared__ float Ks[64][64];    // [d][k] 16KB
    const float* __restrict__ gq = g_qkv[0];
    const float* __restrict__ gk = g_qkv[1];
    const int tid = threadIdx.x;
    const int tx = tid & 15, ty = tid >> 4;
    const int dg = (tid & 15) * 4;

    // load Q tile (transposed into smem)
#pragma unroll
    for (int r = 0; r < 8; ++r) {
        int row = (tid >> 4) + r * 16;
        float4 v = *(const float4*)(gq + ((size_t)(b * LL + q0 + row)) * DD + h * HD + dg);
        Qs[dg + 0][row] = v.x; Qs[dg + 1][row] = v.y;
        Qs[dg + 2][row] = v.z; Qs[dg + 3][row] = v.w;
    }

    float rmax[8], rsum[8];
#pragma unroll
    for (int i = 0; i < 8; ++i) { rmax[i] = -FLT_MAX; rsum[i] = 0.f; }

    for (int kt = 0; kt < LL / 64; ++kt) {
        __syncthreads();
        // load K tile
#pragma unroll
        for (int r = 0; r < 4; ++r) {
            int row = (tid >> 4) + r * 16;
            float4 v = *(const float4*)(gk + ((size_t)(b * LL + kt * 64 + row)) * DD + h * HD + dg);
            Ks[dg + 0][row] = v.x; Ks[dg + 1][row] = v.y;
            Ks[dg + 2][row] = v.z; Ks[dg + 3][row] = v.w;
        }
        __syncthreads();

        float acc[8][4];
#pragma unroll
        for (int i = 0; i < 8; ++i)
#pragma unroll
            for (int j = 0; j < 4; ++j) acc[i][j] = 0.f;

#pragma unroll 16
        for (int d = 0; d < 64; ++d) {
            float a[8], kk[4];
            *(float4*)&a[0] = *(const float4*)&Qs[d][ty * 8];
            *(float4*)&a[4] = *(const float4*)&Qs[d][ty * 8 + 4];
            *(float4*)&kk[0] = *(const float4*)&Ks[d][tx * 4];
#pragma unroll
            for (int i = 0; i < 8; ++i)
#pragma unroll
                for (int j = 0; j < 4; ++j) acc[i][j] += a[i] * kk[j];
        }
#pragma unroll
        for (int i = 0; i < 8; ++i) {
            float m01 = fmaxf(acc[i][0], acc[i][1]);
            float m23 = fmaxf(acc[i][2], acc[i][3]);
            rmax[i] = fmaxf(rmax[i], fmaxf(m01, m23));
            rsum[i] += (acc[i][0] + acc[i][1]) + (acc[i][2] + acc[i][3]);
        }
    }
    // reduce across the 16 tx lanes (threads sharing the same q rows)
#pragma unroll
    for (int i = 0; i < 8; ++i) {
        float m = rmax[i], s = rsum[i];
#pragma unroll
        for (int o = 8; o > 0; o >>= 1) {
            m = fmaxf(m, __shfl_xor_sync(0xffffffffu, m, o));
            s += __shfl_xor_sync(0xffffffffu, s, o);
        }
        if (tx == 0)
            g_sp[((b * HH + h) << 11) + q0 + ty * 8 + i] =
                SCALE * m - SCALE * s * (1.0f / (float)LL);
    }
}

// ---------------- clear selection mask ----------------
__global__ void clear_kernel() {
    int i = blockIdx.x * 256 + threadIdx.x;
    if (i < BB * LL) g_selmask[i] = 0u;
}

// ---------------- top-40 per (b,h) (iterative argmax) ----------------
__global__ __launch_bounds__(256) void topk_kernel() {
    const int bh = blockIdx.x;            // 0..31
    const int b = bh >> 4, h = bh & 15;
    __shared__ float sp[LL];
    __shared__ float rv[8];
    __shared__ int ri[8];
    const int tid = threadIdx.x;
    for (int j = tid; j < LL; j += 256) sp[j] = g_sp[bh * LL + j];
    __syncthreads();

    for (int it = 0; it < TOPU; ++it) {
        float bv = -FLT_MAX; int bi = 1 << 30;
        for (int j = tid; j < LL; j += 256) {
            float v = sp[j];
            if (v > bv || (v == bv && j < bi)) { bv = v; bi = j; }
        }
#pragma unroll
        for (int o = 16; o > 0; o >>= 1) {
            float ov = __shfl_xor_sync(0xffffffffu, bv, o);
            int oi = __shfl_xor_sync(0xffffffffu, bi, o);
            if (ov > bv || (ov == bv && oi < bi)) { bv = ov; bi = oi; }
        }
        if ((tid & 31) == 0) { rv[tid >> 5] = bv; ri[tid >> 5] = bi; }
        __syncthreads();
        if (tid == 0) {
            float mv = -FLT_MAX; int mi = 1 << 30;
            for (int w = 0; w < 8; ++w)
                if (rv[w] > mv || (rv[w] == mv && ri[w] < mi)) { mv = rv[w]; mi = ri[w]; }
            g_topk[bh * TOPU + it] = mi;
            sp[mi] = -FLT_MAX;
            int row = b * LL + mi;
            atomicOr(&g_selmask[row], 1u << h);
            g_selu[row * HH + h] = it;
        }
        __syncthreads();
    }
}

// ---------------- attention over the top queries ----------------
// grid: (TOPU/4, H, B). Each block: 4 top queries, full 2048 keys, softmax, ctx.
__global__ __launch_bounds__(256) void attn_kernel() {
    const int b = blockIdx.z, h = blockIdx.y, ut = blockIdx.x;
    const int bh = b * HH + h;
    __shared__ float Qs[4][64];
    __shared__ float P[4][LL];          // 32KB probs
    __shared__ float red[4][8];
    __shared__ float gmx[4], gsm[4];
    __shared__ float cred[8][4][64];    // 8KB cross-warp ctx reduce
    const float* __restrict__ gq = g_qkv[0];
    const float* __restrict__ gk = g_qkv[1];
    const float* __restrict__ gv = g_qkv[2];
    const int tid = threadIdx.x, lane = tid & 31, wp = tid >> 5;

    {
        int u = tid >> 6, d = tid & 63;
        int qi = g_topk[bh * TOPU + ut * 4 + u];
        Qs[u][d] = gq[((size_t)(b * LL + qi)) * DD + h * HD + d];
    }
    __syncthreads();

    const float* Kb = gk + (size_t)(b * LL) * DD + h * HD;
    float lm[4] = {-FLT_MAX, -FLT_MAX, -FLT_MAX, -FLT_MAX};
#pragma unroll
    for (int j = 0; j < 8; ++j) {
        int k = tid + 256 * j;
        const float4* kr = (const float4*)(Kb + (size_t)k * DD);
        float s[4] = {0.f, 0.f, 0.f, 0.f};
#pragma unroll
        for (int dv = 0; dv < 16; ++dv) {
            float4 kv = kr[dv];
#pragma unroll
            for (int u = 0; u < 4; ++u) {
                s[u] += Qs[u][dv * 4 + 0] * kv.x + Qs[u][dv * 4 + 1] * kv.y +
                        Qs[u][dv * 4 + 2] * kv.z + Qs[u][dv * 4 + 3] * kv.w;
            }
        }
#pragma unroll
        for (int u = 0; u < 4; ++u) {
            float sv = s[u] * SCALE;
            P[u][k] = sv;
            lm[u] = fmaxf(lm[u], sv);
        }
    }
    // global max per u
#pragma unroll
    for (int u = 0; u < 4; ++u) {
#pragma unroll
        for (int o = 16; o > 0; o >>= 1) lm[u] = fmaxf(lm[u], __shfl_xor_sync(0xffffffffu, lm[u], o));
        if (lane == 0) red[u][wp] = lm[u];
    }
    __syncthreads();
    if (tid < 4) {
        float m = red[tid][0];
        for (int w = 1; w < 8; ++w) m = fmaxf(m, red[tid][w]);
        gmx[tid] = m;
    }
    __syncthreads();
    // exp + sum
    float ls[4] = {0.f, 0.f, 0.f, 0.f};
#pragma unroll
    for (int j = 0; j < 8; ++j) {
        int k = tid + 256 * j;
#pragma unroll
        for (int u = 0; u < 4; ++u) {
            float e = expf(P[u][k] - gmx[u]);
            P[u][k] = e;
            ls[u] += e;
        }
    }
#pragma unroll
    for (int u = 0; u < 4; ++u) {
#pragma unroll
        for (int o = 16; o > 0; o >>= 1) ls[u] += __shfl_xor_sync(0xffffffffu, ls[u], o);
        if (lane == 0) red[u][wp] = ls[u];
    }
    __syncthreads();
    if (tid < 4) {
        float s = 0.f;
        for (int w = 0; w < 8; ++w) s += red[tid][w];
        gsm[tid] = s;
    }
    __syncthreads();
    // ctx: warp wp handles key range [wp*256, wp*256+256)
    const float* Vb = gv + (size_t)(b * LL) * DD + h * HD;
    const int d0 = lane * 2;
    float c[4][2] = {{0.f,0.f},{0.f,0.f},{0.f,0.f},{0.f,0.f}};
    const int k0 = wp * 256;
    for (int kk = 0; kk < 256; ++kk) {
        int k = k0 + kk;
        float2 v = *(const float2*)(Vb + (size_t)k * DD + d0);
#pragma unroll
        for (int u = 0; u < 4; ++u) {
            float p = P[u][k];
            c[u][0] += p * v.x;
            c[u][1] += p * v.y;
        }
    }
#pragma unroll
    for (int u = 0; u < 4; ++u) {
        cred[wp][u][d0] = c[u][0];
        cred[wp][u][d0 + 1] = c[u][1];
    }
    __syncthreads();
    {
        int u = tid >> 6, d = tid & 63;
        float s = 0.f;
#pragma unroll
        for (int w = 0; w < 8; ++w) s += cred[w][u][d];
        g_ctx[((size_t)bh * TOPU + ut * 4 + u) * HD + d] = s / gsm[u];
    }
}

// ---------------- base = mean(V) over sequence ----------------
__global__ void base_kernel() {
    int b = blockIdx.y;
    int c = blockIdx.x * 256 + threadIdx.x;
    const float* p = g_qkv[2] + (size_t)b * LL * DD + c;
    float s = 0.f;
    for (int l = 0; l < LL; ++l) s += p[(size_t)l * DD];
    g_base[b * DD + c] = s * (1.0f / (float)LL);
}

// ---------------- base_out = base_row @ Wo^T + bo ----------------
__global__ __launch_bounds__(256) void baseout_kernel(const float* __restrict__ Wo,
                                                      const float* __restrict__ bo) {
    int b = blockIdx.y;
    int n = blockIdx.x * 256 + threadIdx.x;
    __shared__ float br[DD];
    for (int j = threadIdx.x; j < DD; j += 256) br[j] = g_base[b * DD + j];
    __syncthreads();
    const float4* wr = (const float4*)(Wo + (size_t)n * DD);
    const float4* b4 = (const float4*)br;
    float s = bo[n];
    for (int c = 0; c < DD / 4; ++c) {
        float4 w = wr[c], v = b4[c];
        s += w.x * v.x + w.y * v.y + w.z * v.z + w.w * v.w;
    }
    g_baseout[b * DD + n] = s;
}

// ---------------- final output: broadcast base_out + per-row head deltas --------
__global__ __launch_bounds__(256) void output_kernel(const float* __restrict__ Wo,
                                                     float* __restrict__ out) {
    const int row = blockIdx.x;           // b*L + l
    const int b = row >> 11;
    const int tid = threadIdx.x;
    __shared__ float delta[HD];

    float o[4];
    *(float4*)o = *(const float4*)(g_baseout + b * DD + tid * 4);

    unsigned mask = g_selmask[row];
    while (mask) {
        int h = __ffs(mask) - 1;
        mask &= mask - 1;
        int u = g_selu[row * HH + h];
        if (tid < HD) {
            int bh = b * HH + h;
            delta[tid] = g_ctx[((size_t)bh * TOPU + u) * HD + tid] - g_base[b * DD + h * HD + tid];
        }
        __syncthreads();
        const float* wr = Wo + (size_t)tid * 4 * DD + h * HD;
#pragma unroll
        for (int j = 0; j < 4; ++j) {
            const float4* w4 = (const float4*)(wr + (size_t)j * DD);
            float s = 0.f;
#pragma unroll
            for (int d4 = 0; d4 < HD / 4; ++d4) {
                float4 w = w4[d4];
                s += w.x * delta[d4 * 4 + 0] + w.y * delta[d4 * 4 + 1] +
                     w.z * delta[d4 * 4 + 2] + w.w * delta[d4 * 4 + 3];
            }
            o[j] += s;
        }
        __syncthreads();
    }
    *(float4*)(out + (size_t)row * DD + tid * 4) = make_float4(o[0], o[1], o[2], o[3]);
}

// ---------------- launch ----------------
extern "C" void kernel_launch(void* const* d_in, const int* in_sizes, int n_in,
                              void* d_out, int out_size) {
    const float* query = (const float*)d_in[0];
    const float* key_t = (const float*)d_in[1];
    const float* value = (const float*)d_in[2];
    const float* Wq = (const float*)d_in[3];
    const float* bq = (const float*)d_in[4];
    const float* Wk = (const float*)d_in[5];
    const float* bk = (const float*)d_in[6];
    const float* Wv = (const float*)d_in[7];
    const float* bv = (const float*)d_in[8];
    const float* Wo = (const float*)d_in[9];
    const float* bo = (const float*)d_in[10];
    float* out = (float*)d_out;

    dim3 gGemm(DD / 128, MM / 128);
    sgemm_nt<<<gGemm, 256>>>(query, Wq, bq, 0);
    sgemm_nt<<<gGemm, 256>>>(key_t, Wk, bk, 1);
    sgemm_nt<<<gGemm, 256>>>(value, Wv, bv, 2);

    sparsity_kernel<<<dim3(LL / 128, HH, BB), 256>>>();
    clear_kernel<<<(BB * LL + 255) / 256, 256>>>();
    topk_kernel<<<BB * HH, 256>>>();
    attn_kernel<<<dim3(TOPU / 4, HH, BB), 256>>>();
    base_kernel<<<dim3(DD / 256, BB), 256>>>();
    baseout_kernel<<<dim3(DD / 256, BB), 256>>>(Wo, bo);
    output_kernel<<<BB * LL, 256>>>(Wo, out);
}

// round 3
// speedup vs baseline: 1.6974x; 1.6974x over previous
#include <cuda_runtime.h>
#include <cuda_bf16.h>
#include <math.h>
#include <float.h>
#include <stdint.h>

// Problem constants
#define BB 2
#define LL 2048
#define DD 1024
#define HH 16
#define HD 64
#define TOPU 40
#define MM (BB*LL)
#define SCALE 0.125f

// ---------------- scratch ----------------
__device__ float g_qkv[3][MM*DD];
__device__ float g_sp[BB*HH*LL];
__device__ int g_topk[BB*HH*TOPU];
__device__ unsigned g_selmask[BB*LL];
__device__ int g_selu[BB*LL*HH];
__device__ float g_ctx[BB*HH*TOPU*HD];
__device__ float g_base[BB*DD];
__device__ float g_baseout[BB*DD];

// ---------------- helpers ----------------
__device__ __forceinline__ uint32_t smem_u32(const void* p) {
    uint32_t a;
    asm("{ .reg .u64 t; cvta.to.shared.u64 t, %1; cvt.u32.u64 %0, t; }" : "=r"(a) : "l"(p));
    return a;
}

__device__ __forceinline__ void ldsm4(uint32_t r[4], uint32_t addr) {
    asm volatile("ldmatrix.sync.aligned.m8n8.x4.shared.b16 {%0,%1,%2,%3}, [%4];"
        : "=r"(r[0]), "=r"(r[1]), "=r"(r[2]), "=r"(r[3]) : "r"(addr));
}

__device__ __forceinline__ void mma16816(float c[4], const uint32_t a[4], const uint32_t b[2]) {
    asm volatile("mma.sync.aligned.m16n8k16.row.col.f32.bf16.bf16.f32 "
        "{%0,%1,%2,%3},{%4,%5,%6,%7},{%8,%9},{%0,%1,%2,%3};"
        : "+f"(c[0]), "+f"(c[1]), "+f"(c[2]), "+f"(c[3])
        : "r"(a[0]), "r"(a[1]), "r"(a[2]), "r"(a[3]), "r"(b[0]), "r"(b[1]));
}

// fp32x4 -> packed bf16 hi plane + lo plane (2-way split)
__device__ __forceinline__ void split_pack(float4 v, uint2& hi, uint2& lo) {
    __nv_bfloat16 bx = __float2bfloat16_rn(v.x);
    __nv_bfloat16 by = __float2bfloat16_rn(v.y);
    __nv_bfloat16 bz = __float2bfloat16_rn(v.z);
    __nv_bfloat16 bw = __float2bfloat16_rn(v.w);
    hi.x = ((uint32_t)__bfloat16_as_ushort(by) << 16) | __bfloat16_as_ushort(bx);
    hi.y = ((uint32_t)__bfloat16_as_ushort(bw) << 16) | __bfloat16_as_ushort(bz);
    __nv_bfloat16 lx = __float2bfloat16_rn(v.x - __bfloat162float(bx));
    __nv_bfloat16 ly = __float2bfloat16_rn(v.y - __bfloat162float(by));
    __nv_bfloat16 lz = __float2bfloat16_rn(v.z - __bfloat162float(bz));
    __nv_bfloat16 lw = __float2bfloat16_rn(v.w - __bfloat162float(bw));
    lo.x = ((uint32_t)__bfloat16_as_ushort(ly) << 16) | __bfloat16_as_ushort(lx);
    lo.y = ((uint32_t)__bfloat16_as_ushort(lw) << 16) | __bfloat16_as_ushort(lz);
}

// ================= fused projections: Y_z = X_z @ W_z^T + b_z =================
// grid (8 ntiles, 32 mtiles, 3), 256 threads. Tile 128x128, K-chunk 32.
// smem/buf: Ah[10240] Al[10240] Bh[10240] Bl[10240] (row stride 80B); 2 bufs.
#define PROJ_BUF 40960
#define PROJ_DSMEM (2*PROJ_BUF + 256)

__global__ __launch_bounds__(256, 1) void proj_mma(
    const float* __restrict__ X0, const float* __restrict__ X1, const float* __restrict__ X2,
    const float* __restrict__ W0, const float* __restrict__ W1, const float* __restrict__ W2,
    const float* __restrict__ bi0, const float* __restrict__ bi1, const float* __restrict__ bi2) {
    extern __shared__ char dsm[];
    char* sm = (char*)(((uintptr_t)dsm + 255) & ~(uintptr_t)255);
    const uint32_t sb = smem_u32(sm);
    const int z = blockIdx.z;
    const float* X = (z == 0) ? X0 : (z == 1) ? X1 : X2;
    const float* W = (z == 0) ? W0 : (z == 1) ? W1 : W2;
    const float* bias = (z == 0) ? bi0 : (z == 1) ? bi1 : bi2;
    float* __restrict__ Y = g_qkv[z];
    const int tid = threadIdx.x, lane = tid & 31, wid = tid >> 5;
    const int bm = blockIdx.y * 128, bn = blockIdx.x * 128;
    const int m0 = (wid >> 2) * 64, n0 = (wid & 3) * 32;

    float4 pa[4], pb[4];
    float c[4][4][4];
#pragma unroll
    for (int i = 0; i < 4; ++i)
#pragma unroll
        for (int j = 0; j < 4; ++j)
#pragma unroll
            for (int k = 0; k < 4; ++k) c[i][j][k] = 0.f;

    auto ldg_chunk = [&](int kt) {
#pragma unroll
        for (int i = 0; i < 4; ++i) {
            int idx = tid + 256 * i, r = idx >> 3, c4 = (idx & 7) << 2;
            pa[i] = *(const float4*)(X + (size_t)(bm + r) * DD + kt * 32 + c4);
            pb[i] = *(const float4*)(W + (size_t)(bn + r) * DD + kt * 32 + c4);
        }
    };
    auto sts_chunk = [&](int buf) {
        char* base = sm + buf * PROJ_BUF;
#pragma unroll
        for (int i = 0; i < 4; ++i) {
            int idx = tid + 256 * i, r = idx >> 3, c4 = (idx & 7) << 2;
            uint32_t off = r * 80 + c4 * 2;
            uint2 hi, lo;
            split_pack(pa[i], hi, lo);
            *(uint2*)(base + off) = hi;
            *(uint2*)(base + 10240 + off) = lo;
            split_pack(pb[i], hi, lo);
            *(uint2*)(base + 20480 + off) = hi;
            *(uint2*)(base + 30720 + off) = lo;
        }
    };

    ldg_chunk(0);
    sts_chunk(0);
    ldg_chunk(1);
    __syncthreads();

    const uint32_t arow = (uint32_t)(m0 + (lane & 15)) * 80 + ((lane & 16) ? 16 : 0);
    const uint32_t brow0 = (uint32_t)(n0 + (lane & 15)) * 80 + ((lane & 16) ? 16 : 0);
    const uint32_t brow1 = (uint32_t)(n0 + 16 + (lane & 15)) * 80 + ((lane & 16) ? 16 : 0);

#pragma unroll 1
    for (int kt = 0; kt < 32; ++kt) {
        const int buf = kt & 1;
        const uint32_t A = sb + buf * PROJ_BUF;
#pragma unroll
        for (int s = 0; s < 2; ++s) {
            const uint32_t ko = s * 32;
            uint32_t ah[4][4], al[4][4], bh[4][2], bl[4][2];
#pragma unroll
            for (int i = 0; i < 4; ++i) {
                ldsm4(ah[i], A + arow + i * 1280 + ko);
                ldsm4(al[i], A + 10240 + arow + i * 1280 + ko);
            }
            {
                uint32_t q[4];
                ldsm4(q, A + 20480 + brow0 + ko);
                bh[0][0] = q[0]; bh[0][1] = q[2]; bh[1][0] = q[1]; bh[1][1] = q[3];
                ldsm4(q, A + 20480 + brow1 + ko);
                bh[2][0] = q[0]; bh[2][1] = q[2]; bh[3][0] = q[1]; bh[3][1] = q[3];
                ldsm4(q, A + 30720 + brow0 + ko);
                bl[0][0] = q[0]; bl[0][1] = q[2]; bl[1][0] = q[1]; bl[1][1] = q[3];
                ldsm4(q, A + 30720 + brow1 + ko);
                bl[2][0] = q[0]; bl[2][1] = q[2]; bl[3][0] = q[1]; bl[3][1] = q[3];
            }
#pragma unroll
            for (int i = 0; i < 4; ++i)
#pragma unroll
                for (int j = 0; j < 4; ++j) {
                    mma16816(c[i][j], ah[i], bh[j]);
                    mma16816(c[i][j], ah[i], bl[j]);
                    mma16816(c[i][j], al[i], bh[j]);
                }
        }
        if (kt < 31) {
            sts_chunk(buf ^ 1);
            if (kt < 30) ldg_chunk(kt + 2);
        }
        __syncthreads();
    }

    // epilogue: fragments -> gmem with bias
#pragma unroll
    for (int i = 0; i < 4; ++i) {
        int r0 = bm + m0 + i * 16 + (lane >> 2);
#pragma unroll
        for (int j = 0; j < 4; ++j) {
            int col = bn + n0 + j * 8 + (lane & 3) * 2;
            float bx = bias[col], by = bias[col + 1];
            *(float2*)(Y + (size_t)r0 * DD + col) = make_float2(c[i][j][0] + bx, c[i][j][1] + by);
            *(float2*)(Y + (size_t)(r0 + 8) * DD + col) = make_float2(c[i][j][2] + bx, c[i][j][3] + by);
        }
    }
}

// ================= sparsity via mma.sync: per-q max & mean of Q K^T ===========
// grid (16 qtiles, 16 h, 2 b), 256 thr. Q (128x64) resident; K chunks of 128
// keys double-buffered; scores folded into per-row max/sum registers.
#define SP_QL 18432
#define SP_K0 36864
#define SP_KSZ 36864
#define SP_DSMEM (SP_K0 + 2*SP_KSZ + 256)

__global__ __launch_bounds__(256, 1) void sparsity_mma() {
    extern __shared__ char dsm[];
    char* sm = (char*)(((uintptr_t)dsm + 255) & ~(uintptr_t)255);
    const uint32_t sb = smem_u32(sm);
    __shared__ float sred[2][128][4];
    const int tid = threadIdx.x, lane = tid & 31, wid = tid >> 5;
    const int b = blockIdx.z, h = blockIdx.y, q0 = blockIdx.x * 128;
    const float* __restrict__ gq = g_qkv[0] + (size_t)(b * LL + q0) * DD + h * HD;
    const float* __restrict__ gk = g_qkv[1] + (size_t)(b * LL) * DD + h * HD;
    const int m0 = (wid >> 2) * 64, n0 = (wid & 3) * 32;

    // load Q tile into resident planes (row stride 144B)
#pragma unroll
    for (int i = 0; i < 8; ++i) {
        int idx = tid + 256 * i, r = idx >> 4, c4 = (idx & 15) << 2;
        float4 v = *(const float4*)(gq + (size_t)r * DD + c4);
        uint2 hi, lo;
        split_pack(v, hi, lo);
        uint32_t off = r * 144 + c4 * 2;
        *(uint2*)(sm + off) = hi;
        *(uint2*)(sm + SP_QL + off) = lo;
    }

    float4 pk[8];
    auto ldg_chunk = [&](int kt) {
#pragma unroll
        for (int i = 0; i < 8; ++i) {
            int idx = tid + 256 * i, r = idx >> 4, c4 = (idx & 15) << 2;
            pk[i] = *(const float4*)(gk + (size_t)(kt * 128 + r) * DD + c4);
        }
    };
    auto sts_chunk = [&](int buf) {
        char* base = sm + SP_K0 + buf * SP_KSZ;
#pragma unroll
        for (int i = 0; i < 8; ++i) {
            int idx = tid + 256 * i, r = idx >> 4, c4 = (idx & 15) << 2;
            uint2 hi, lo;
            split_pack(pk[i], hi, lo);
            uint32_t off = r * 144 + c4 * 2;
            *(uint2*)(base + off) = hi;
            *(uint2*)(base + 18432 + off) = lo;
        }
    };

    ldg_chunk(0);
    sts_chunk(0);
    ldg_chunk(1);
    __syncthreads();

    float rmax[8], rsum[8];
#pragma unroll
    for (int s = 0; s < 8; ++s) { rmax[s] = -FLT_MAX; rsum[s] = 0.f; }

    const uint32_t arow = (uint32_t)(m0 + (lane & 15)) * 144 + ((lane & 16) ? 16 : 0);
    const uint32_t brow0 = (uint32_t)(n0 + (lane & 15)) * 144 + ((lane & 16) ? 16 : 0);
    const uint32_t brow1 = (uint32_t)(n0 + 16 + (lane & 15)) * 144 + ((lane & 16) ? 16 : 0);

#pragma unroll 1
    for (int kt = 0; kt < 16; ++kt) {
        const int buf = kt & 1;
        const uint32_t K = sb + SP_K0 + buf * SP_KSZ;
        float c[4][4][4];
#pragma unroll
        for (int i = 0; i < 4; ++i)
#pragma unroll
            for (int j = 0; j < 4; ++j)
#pragma unroll
                for (int k = 0; k < 4; ++k) c[i][j][k] = 0.f;

#pragma unroll
        for (int s = 0; s < 4; ++s) {
            const uint32_t ko = s * 32;
            uint32_t ah[4][4], al[4][4], bh[4][2], bl[4][2];
#pragma unroll
            for (int i = 0; i < 4; ++i) {
                ldsm4(ah[i], sb + arow + i * 2304 + ko);
                ldsm4(al[i], sb + SP_QL + arow + i * 2304 + ko);
            }
            {
                uint32_t q[4];
                ldsm4(q, K + brow0 + ko);
                bh[0][0] = q[0]; bh[0][1] = q[2]; bh[1][0] = q[1]; bh[1][1] = q[3];
                ldsm4(q, K + brow1 + ko);
                bh[2][0] = q[0]; bh[2][1] = q[2]; bh[3][0] = q[1]; bh[3][1] = q[3];
                ldsm4(q, K + 18432 + brow0 + ko);
                bl[0][0] = q[0]; bl[0][1] = q[2]; bl[1][0] = q[1]; bl[1][1] = q[3];
                ldsm4(q, K + 18432 + brow1 + ko);
                bl[2][0] = q[0]; bl[2][1] = q[2]; bl[3][0] = q[1]; bl[3][1] = q[3];
            }
#pragma unroll
            for (int i = 0; i < 4; ++i)
#pragma unroll
                for (int j = 0; j < 4; ++j) {
                    mma16816(c[i][j], ah[i], bh[j]);
                    mma16816(c[i][j], ah[i], bl[j]);
                    mma16816(c[i][j], al[i], bh[j]);
                }
        }
        // fold scores into per-row running max / sum
#pragma unroll
        for (int i = 0; i < 4; ++i)
#pragma unroll
            for (int hh = 0; hh < 2; ++hh) {
                float m = -FLT_MAX, su = 0.f;
#pragma unroll
                for (int j = 0; j < 4; ++j) {
                    float x = c[i][j][hh * 2], y = c[i][j][hh * 2 + 1];
                    m = fmaxf(m, fmaxf(x, y));
                    su += x + y;
                }
                rmax[i * 2 + hh] = fmaxf(rmax[i * 2 + hh], m);
                rsum[i * 2 + hh] += su;
            }
        if (kt < 15) {
            sts_chunk(buf ^ 1);
            if (kt < 14) ldg_chunk(kt + 2);
        }
        __syncthreads();
    }

    // reduce across quad lanes (different n columns, same row)
#pragma unroll
    for (int s = 0; s < 8; ++s) {
        rmax[s] = fmaxf(rmax[s], __shfl_xor_sync(0xffffffffu, rmax[s], 1));
        rmax[s] = fmaxf(rmax[s], __shfl_xor_sync(0xffffffffu, rmax[s], 2));
        rsum[s] += __shfl_xor_sync(0xffffffffu, rsum[s], 1);
        rsum[s] += __shfl_xor_sync(0xffffffffu, rsum[s], 2);
    }
    if ((lane & 3) == 0) {
#pragma unroll
        for (int i = 0; i < 4; ++i)
#pragma unroll
            for (int hh = 0; hh < 2; ++hh) {
                int row = m0 + i * 16 + hh * 8 + (lane >> 2);
                sred[0][row][wid & 3] = rmax[i * 2 + hh];
                sred[1][row][wid & 3] = rsum[i * 2 + hh];
            }
    }
    __syncthreads();
    if (tid < 128) {
        float m = fmaxf(fmaxf(sred[0][tid][0], sred[0][tid][1]),
                        fmaxf(sred[0][tid][2], sred[0][tid][3]));
        float su = sred[1][tid][0] + sred[1][tid][1] + sred[1][tid][2] + sred[1][tid][3];
        g_sp[(b * HH + h) * LL + q0 + tid] = SCALE * m - SCALE * su * (1.0f / (float)LL);
    }
}

// ---------------- clear selection mask ----------------
__global__ void clear_kernel() {
    int i = blockIdx.x * 256 + threadIdx.x;
    if (i < BB * LL) g_selmask[i] = 0u;
}

// ---------------- top-40 per (b,h) ----------------
__global__ __launch_bounds__(256) void topk_kernel() {
    const int bh = blockIdx.x;
    const int b = bh >> 4, h = bh & 15;
    __shared__ float sp[LL];
    __shared__ float rv[8];
    __shared__ int ri[8];
    const int tid = threadIdx.x;
    for (int j = tid; j < LL; j += 256) sp[j] = g_sp[bh * LL + j];
    __syncthreads();
    for (int it = 0; it < TOPU; ++it) {
        float bv = -FLT_MAX; int bi = 1 << 30;
        for (int j = tid; j < LL; j += 256) {
            float v = sp[j];
            if (v > bv || (v == bv && j < bi)) { bv = v; bi = j; }
        }
#pragma unroll
        for (int o = 16; o > 0; o >>= 1) {
            float ov = __shfl_xor_sync(0xffffffffu, bv, o);
            int oi = __shfl_xor_sync(0xffffffffu, bi, o);
            if (ov > bv || (ov == bv && oi < bi)) { bv = ov; bi = oi; }
        }
        if ((tid & 31) == 0) { rv[tid >> 5] = bv; ri[tid >> 5] = bi; }
        __syncthreads();
        if (tid == 0) {
            float mv = -FLT_MAX; int mi = 1 << 30;
            for (int w = 0; w < 8; ++w)
                if (rv[w] > mv || (rv[w] == mv && ri[w] < mi)) { mv = rv[w]; mi = ri[w]; }
            g_topk[bh * TOPU + it] = mi;
            sp[mi] = -FLT_MAX;
            int row = b * LL + mi;
            atomicOr(&g_selmask[row], 1u << h);
            g_selu[row * HH + h] = it;
        }
        __syncthreads();
    }
}

// ---------------- attention over the top queries ----------------
__global__ __launch_bounds__(256) void attn_kernel() {
    const int b = blockIdx.z, h = blockIdx.y, ut = blockIdx.x;
    const int bh = b * HH + h;
    __shared__ float Qs[4][64];
    __shared__ float P[4][LL];
    __shared__ float red[4][8];
    __shared__ float gmx[4], gsm[4];
    __shared__ float cred[8][4][64];
    const float* __restrict__ gq = g_qkv[0];
    const float* __restrict__ gk = g_qkv[1];
    const float* __restrict__ gv = g_qkv[2];
    const int tid = threadIdx.x, lane = tid & 31, wp = tid >> 5;
    {
        int u = tid >> 6, d = tid & 63;
        int qi = g_topk[bh * TOPU + ut * 4 + u];
        Qs[u][d] = gq[((size_t)(b * LL + qi)) * DD + h * HD + d];
    }
    __syncthreads();
    const float* Kb = gk + (size_t)(b * LL) * DD + h * HD;
    float lm[4] = {-FLT_MAX, -FLT_MAX, -FLT_MAX, -FLT_MAX};
#pragma unroll
    for (int j = 0; j < 8; ++j) {
        int k = tid + 256 * j;
        const float4* kr = (const float4*)(Kb + (size_t)k * DD);
        float s[4] = {0.f, 0.f, 0.f, 0.f};
#pragma unroll
        for (int dv = 0; dv < 16; ++dv) {
            float4 kv = kr[dv];
#pragma unroll
            for (int u = 0; u < 4; ++u)
                s[u] += Qs[u][dv * 4 + 0] * kv.x + Qs[u][dv * 4 + 1] * kv.y +
                        Qs[u][dv * 4 + 2] * kv.z + Qs[u][dv * 4 + 3] * kv.w;
        }
#pragma unroll
        for (int u = 0; u < 4; ++u) {
            float sv = s[u] * SCALE;
            P[u][k] = sv;
            lm[u] = fmaxf(lm[u], sv);
        }
    }
#pragma unroll
    for (int u = 0; u < 4; ++u) {
#pragma unroll
        for (int o = 16; o > 0; o >>= 1) lm[u] = fmaxf(lm[u], __shfl_xor_sync(0xffffffffu, lm[u], o));
        if (lane == 0) red[u][wp] = lm[u];
    }
    __syncthreads();
    if (tid < 4) {
        float m = red[tid][0];
        for (int w = 1; w < 8; ++w) m = fmaxf(m, red[tid][w]);
        gmx[tid] = m;
    }
    __syncthreads();
    float ls[4] = {0.f, 0.f, 0.f, 0.f};
#pragma unroll
    for (int j = 0; j < 8; ++j) {
        int k = tid + 256 * j;
#pragma unroll
        for (int u = 0; u < 4; ++u) {
            float e = expf(P[u][k] - gmx[u]);
            P[u][k] = e;
            ls[u] += e;
        }
    }
#pragma unroll
    for (int u = 0; u < 4; ++u) {
#pragma unroll
        for (int o = 16; o > 0; o >>= 1) ls[u] += __shfl_xor_sync(0xffffffffu, ls[u], o);
        if (lane == 0) red[u][wp] = ls[u];
    }
    __syncthreads();
    if (tid < 4) {
        float s = 0.f;
        for (int w = 0; w < 8; ++w) s += red[tid][w];
        gsm[tid] = s;
    }
    __syncthreads();
    const float* Vb = gv + (size_t)(b * LL) * DD + h * HD;
    const int d0 = lane * 2;
    float c[4][2] = {{0.f,0.f},{0.f,0.f},{0.f,0.f},{0.f,0.f}};
    const int k0 = wp * 256;
    for (int kk = 0; kk < 256; ++kk) {
        int k = k0 + kk;
        float2 v = *(const float2*)(Vb + (size_t)k * DD + d0);
#pragma unroll
        for (int u = 0; u < 4; ++u) {
            float p = P[u][k];
            c[u][0] += p * v.x;
            c[u][1] += p * v.y;
        }
    }
#pragma unroll
    for (int u = 0; u < 4; ++u) {
        cred[wp][u][d0] = c[u][0];
        cred[wp][u][d0 + 1] = c[u][1];
    }
    __syncthreads();
    {
        int u = tid >> 6, d = tid & 63;
        float s = 0.f;
#pragma unroll
        for (int w = 0; w < 8; ++w) s += cred[w][u][d];
        g_ctx[((size_t)bh * TOPU + ut * 4 + u) * HD + d] = s / gsm[u];
    }
}

// ---------------- base = mean(V) over sequence ----------------
__global__ void base_kernel() {
    int b = blockIdx.y;
    int c = blockIdx.x * 256 + threadIdx.x;
    const float* p = g_qkv[2] + (size_t)b * LL * DD + c;
    float s = 0.f;
    for (int l = 0; l < LL; ++l) s += p[(size_t)l * DD];
    g_base[b * DD + c] = s * (1.0f / (float)LL);
}

// ---------------- base_out = base_row @ Wo^T + bo ----------------
__global__ __launch_bounds__(256) void baseout_kernel(const float* __restrict__ Wo,
                                                      const float* __restrict__ bo) {
    int b = blockIdx.y;
    int n = blockIdx.x * 256 + threadIdx.x;
    __shared__ float br[DD];
    for (int j = threadIdx.x; j < DD; j += 256) br[j] = g_base[b * DD + j];
    __syncthreads();
    const float4* wr = (const float4*)(Wo + (size_t)n * DD);
    const float4* b4 = (const float4*)br;
    float s = bo[n];
    for (int c = 0; c < DD / 4; ++c) {
        float4 w = wr[c], v = b4[c];
        s += w.x * v.x + w.y * v.y + w.z * v.z + w.w * v.w;
    }
    g_baseout[b * DD + n] = s;
}

// ---------------- final output ----------------
__global__ __launch_bounds__(256) void output_kernel(const float* __restrict__ Wo,
                                                     float* __restrict__ out) {
    const int row = blockIdx.x;
    const int b = row >> 11;
    const int tid = threadIdx.x;
    __shared__ float delta[HD];
    float o[4];
    *(float4*)o = *(const float4*)(g_baseout + b * DD + tid * 4);
    unsigned mask = g_selmask[row];
    while (mask) {
        int h = __ffs(mask) - 1;
        mask &= mask - 1;
        int u = g_selu[row * HH + h];
        if (tid < HD) {
            int bh = b * HH + h;
            delta[tid] = g_ctx[((size_t)bh * TOPU + u) * HD + tid] - g_base[b * DD + h * HD + tid];
        }
        __syncthreads();
        const float* wr = Wo + (size_t)tid * 4 * DD + h * HD;
#pragma unroll
        for (int j = 0; j < 4; ++j) {
            const float4* w4 = (const float4*)(wr + (size_t)j * DD);
            float s = 0.f;
#pragma unroll
            for (int d4 = 0; d4 < HD / 4; ++d4) {
                float4 w = w4[d4];
                s += w.x * delta[d4 * 4 + 0] + w.y * delta[d4 * 4 + 1] +
                     w.z * delta[d4 * 4 + 2] + w.w * delta[d4 * 4 + 3];
            }
            o[j] += s;
        }
        __syncthreads();
    }
    *(float4*)(out + (size_t)row * DD + tid * 4) = make_float4(o[0], o[1], o[2], o[3]);
}

// ---------------- launch ----------------
extern "C" void kernel_launch(void* const* d_in, const int* in_sizes, int n_in,
                              void* d_out, int out_size) {
    const float* query = (const float*)d_in[0];
    const float* key_t = (const float*)d_in[1];
    const float* value = (const float*)d_in[2];
    const float* Wq = (const float*)d_in[3];
    const float* bq = (const float*)d_in[4];
    const float* Wk = (const float*)d_in[5];
    const float* bk = (const float*)d_in[6];
    const float* Wv = (const float*)d_in[7];
    const float* bv = (const float*)d_in[8];
    const float* Wo = (const float*)d_in[9];
    const float* bo = (const float*)d_in[10];
    float* out = (float*)d_out;

    cudaFuncSetAttribute(proj_mma, cudaFuncAttributeMaxDynamicSharedMemorySize, PROJ_DSMEM);
    cudaFuncSetAttribute(sparsity_mma, cudaFuncAttributeMaxDynamicSharedMemorySize, SP_DSMEM);

    proj_mma<<<dim3(8, 32, 3), 256, PROJ_DSMEM>>>(query, key_t, value, Wq, Wk, Wv, bq, bk, bv);
    sparsity_mma<<<dim3(LL / 128, HH, BB), 256, SP_DSMEM>>>();
    clear_kernel<<<(BB * LL + 255) / 256, 256>>>();
    topk_kernel<<<BB * HH, 256>>>();
    attn_kernel<<<dim3(TOPU / 4, HH, BB), 256>>>();
    base_kernel<<<dim3(DD / 256, BB), 256>>>();
    baseout_kernel<<<dim3(DD / 256, BB), 256>>>(Wo, bo);
    output_kernel<<<BB * LL, 256>>>(Wo, out);
}

// round 4
// speedup vs baseline: 1.7669x; 1.0409x over previous
#include <cuda_runtime.h>
#include <cuda_bf16.h>
#include <math.h>
#include <float.h>
#include <stdint.h>

// Problem constants
#define BB 2
#define LL 2048
#define DD 1024
#define HH 16
#define HD 64
#define TOPU 40
#define MM (BB*LL)
#define SCALE 0.125f

// ---------------- scratch ----------------
__device__ float g_qkv[3][MM*DD];
__device__ __nv_bfloat16 g_xh[3][MM*DD];
__device__ __nv_bfloat16 g_xl[3][MM*DD];
__device__ __nv_bfloat16 g_wh[3][DD*DD];
__device__ __nv_bfloat16 g_wl[3][DD*DD];
__device__ __nv_bfloat16 g_qkh[2][MM*DD];   // bf16 planes of projected Q,K
__device__ __nv_bfloat16 g_qkl[2][MM*DD];
__device__ float g_sp[BB*HH*LL];
__device__ int g_topk[BB*HH*TOPU];
__device__ unsigned g_selmask[BB*LL];
__device__ int g_selu[BB*LL*HH];
__device__ float g_ctx[BB*HH*TOPU*HD];
__device__ float g_base[BB*DD];
__device__ float g_baseout[BB*DD];

// ---------------- helpers ----------------
__device__ __forceinline__ uint32_t smem_u32(const void* p) {
    uint32_t a;
    asm("{ .reg .u64 t; cvta.to.shared.u64 t, %1; cvt.u32.u64 %0, t; }" : "=r"(a) : "l"(p));
    return a;
}
__device__ __forceinline__ void ldsm4(uint32_t r[4], uint32_t addr) {
    asm volatile("ldmatrix.sync.aligned.m8n8.x4.shared.b16 {%0,%1,%2,%3}, [%4];"
        : "=r"(r[0]), "=r"(r[1]), "=r"(r[2]), "=r"(r[3]) : "r"(addr));
}
__device__ __forceinline__ void mma16816(float c[4], const uint32_t a[4], const uint32_t b[2]) {
    asm volatile("mma.sync.aligned.m16n8k16.row.col.f32.bf16.bf16.f32 "
        "{%0,%1,%2,%3},{%4,%5,%6,%7},{%8,%9},{%0,%1,%2,%3};"
        : "+f"(c[0]), "+f"(c[1]), "+f"(c[2]), "+f"(c[3])
        : "r"(a[0]), "r"(a[1]), "r"(a[2]), "r"(a[3]), "r"(b[0]), "r"(b[1]));
}
__device__ __forceinline__ void cpa16(uint32_t dst, const void* src) {
    asm volatile("cp.async.cg.shared.global [%0], [%1], 16;" :: "r"(dst), "l"(src) : "memory");
}
__device__ __forceinline__ void cpa_commit() {
    asm volatile("cp.async.commit_group;" ::: "memory");
}
template <int N> __device__ __forceinline__ void cpa_wait() {
    asm volatile("cp.async.wait_group %0;" :: "n"(N) : "memory");
}

// fp32x4 -> packed bf16 hi plane + lo plane (2-way split)
__device__ __forceinline__ void split_pack(float4 v, uint2& hi, uint2& lo) {
    __nv_bfloat16 bx = __float2bfloat16_rn(v.x);
    __nv_bfloat16 by = __float2bfloat16_rn(v.y);
    __nv_bfloat16 bz = __float2bfloat16_rn(v.z);
    __nv_bfloat16 bw = __float2bfloat16_rn(v.w);
    hi.x = ((uint32_t)__bfloat16_as_ushort(by) << 16) | __bfloat16_as_ushort(bx);
    hi.y = ((uint32_t)__bfloat16_as_ushort(bw) << 16) | __bfloat16_as_ushort(bz);
    __nv_bfloat16 lx = __float2bfloat16_rn(v.x - __bfloat162float(bx));
    __nv_bfloat16 ly = __float2bfloat16_rn(v.y - __bfloat162float(by));
    __nv_bfloat16 lz = __float2bfloat16_rn(v.z - __bfloat162float(bz));
    __nv_bfloat16 lw = __float2bfloat16_rn(v.w - __bfloat162float(bw));
    lo.x = ((uint32_t)__bfloat16_as_ushort(ly) << 16) | __bfloat16_as_ushort(lx);
    lo.y = ((uint32_t)__bfloat16_as_ushort(lw) << 16) | __bfloat16_as_ushort(lz);
}

// ================= split inputs once: fp32 -> (hi, lo) bf16 planes ===========
__global__ __launch_bounds__(256) void split_kernel(
    const float* __restrict__ q, const float* __restrict__ k, const float* __restrict__ v,
    const float* __restrict__ wq, const float* __restrict__ wk, const float* __restrict__ wv) {
    const int sid = blockIdx.y;
    const float* s;
    __nv_bfloat16 *dh, *dl;
    int n4;
    switch (sid) {
        case 0: s = q;  dh = g_xh[0]; dl = g_xl[0]; n4 = MM * DD / 4; break;
        case 1: s = k;  dh = g_xh[1]; dl = g_xl[1]; n4 = MM * DD / 4; break;
        case 2: s = v;  dh = g_xh[2]; dl = g_xl[2]; n4 = MM * DD / 4; break;
        case 3: s = wq; dh = g_wh[0]; dl = g_wl[0]; n4 = DD * DD / 4; break;
        case 4: s = wk; dh = g_wh[1]; dl = g_wl[1]; n4 = DD * DD / 4; break;
        default: s = wv; dh = g_wh[2]; dl = g_wl[2]; n4 = DD * DD / 4; break;
    }
    int idx = blockIdx.x * 256 + threadIdx.x;
    if (idx >= n4) return;
    float4 val = ((const float4*)s)[idx];
    uint2 hi, lo;
    split_pack(val, hi, lo);
    ((uint2*)dh)[idx] = hi;
    ((uint2*)dl)[idx] = lo;
}

// ================= fused projections via cp.async + mma.sync ==================
// grid (8 ntiles, 32 mtiles, 3), 256 threads. Tile 128x128, K-chunk 32, 4 stages.
// stage layout: Ah[10240] Al[10240] Bh[10240] Bl[10240] (row stride 80B).
#define PROJ_STG 40960
#define PROJ_DSMEM (4*PROJ_STG)

__global__ __launch_bounds__(256, 1) void proj_mma(
    const float* __restrict__ bi0, const float* __restrict__ bi1, const float* __restrict__ bi2) {
    extern __shared__ char sm[];
    const uint32_t sb = smem_u32(sm);
    const int z = blockIdx.z;
    const __nv_bfloat16* __restrict__ Xh = g_xh[z];
    const __nv_bfloat16* __restrict__ Xl = g_xl[z];
    const __nv_bfloat16* __restrict__ Wh = g_wh[z];
    const __nv_bfloat16* __restrict__ Wl = g_wl[z];
    const float* bias = (z == 0) ? bi0 : (z == 1) ? bi1 : bi2;
    float* __restrict__ Y = g_qkv[z];
    const int tid = threadIdx.x, lane = tid & 31, wid = tid >> 5;
    const int bm = blockIdx.y * 128, bn = blockIdx.x * 128;
    const int m0 = (wid >> 2) * 64, n0 = (wid & 3) * 32;

    float c[4][4][4];
#pragma unroll
    for (int i = 0; i < 4; ++i)
#pragma unroll
        for (int j = 0; j < 4; ++j)
#pragma unroll
            for (int k = 0; k < 4; ++k) c[i][j][k] = 0.f;

    auto issue = [&](int kt) {
        uint32_t base = sb + (uint32_t)(kt & 3) * PROJ_STG;
#pragma unroll
        for (int i = 0; i < 2; ++i) {
            int idx = tid + 256 * i;
            int r = idx >> 2, seg = idx & 3;
            uint32_t doff = (uint32_t)r * 80 + seg * 16;
            size_t sa = (size_t)(bm + r) * DD + kt * 32 + seg * 8;
            size_t sw = (size_t)(bn + r) * DD + kt * 32 + seg * 8;
            cpa16(base + doff, Xh + sa);
            cpa16(base + 10240 + doff, Xl + sa);
            cpa16(base + 20480 + doff, Wh + sw);
            cpa16(base + 30720 + doff, Wl + sw);
        }
        cpa_commit();
    };

    issue(0); issue(1); issue(2);

    const uint32_t arow = (uint32_t)(m0 + (lane & 15)) * 80 + ((lane & 16) ? 16 : 0);
    const uint32_t brow0 = (uint32_t)(n0 + (lane & 15)) * 80 + ((lane & 16) ? 16 : 0);
    const uint32_t brow1 = (uint32_t)(n0 + 16 + (lane & 15)) * 80 + ((lane & 16) ? 16 : 0);

#pragma unroll 1
    for (int kt = 0; kt < 32; ++kt) {
        if (kt + 3 < 32) issue(kt + 3);
        if (kt <= 28) cpa_wait<3>();
        else if (kt == 29) cpa_wait<2>();
        else if (kt == 30) cpa_wait<1>();
        else cpa_wait<0>();
        __syncthreads();

        const uint32_t A = sb + (uint32_t)(kt & 3) * PROJ_STG;
#pragma unroll
        for (int s = 0; s < 2; ++s) {
            const uint32_t ko = s * 32;
            uint32_t ah[4][4], al[4][4], bh[4][2], bl[4][2];
#pragma unroll
            for (int i = 0; i < 4; ++i) {
                ldsm4(ah[i], A + arow + i * 1280 + ko);
                ldsm4(al[i], A + 10240 + arow + i * 1280 + ko);
            }
            {
                uint32_t qr[4];
                ldsm4(qr, A + 20480 + brow0 + ko);
                bh[0][0] = qr[0]; bh[0][1] = qr[2]; bh[1][0] = qr[1]; bh[1][1] = qr[3];
                ldsm4(qr, A + 20480 + brow1 + ko);
                bh[2][0] = qr[0]; bh[2][1] = qr[2]; bh[3][0] = qr[1]; bh[3][1] = qr[3];
                ldsm4(qr, A + 30720 + brow0 + ko);
                bl[0][0] = qr[0]; bl[0][1] = qr[2]; bl[1][0] = qr[1]; bl[1][1] = qr[3];
                ldsm4(qr, A + 30720 + brow1 + ko);
                bl[2][0] = qr[0]; bl[2][1] = qr[2]; bl[3][0] = qr[1]; bl[3][1] = qr[3];
            }
#pragma unroll
            for (int i = 0; i < 4; ++i)
#pragma unroll
                for (int j = 0; j < 4; ++j) {
                    mma16816(c[i][j], ah[i], bh[j]);
                    mma16816(c[i][j], ah[i], bl[j]);
                    mma16816(c[i][j], al[i], bh[j]);
                }
        }
        __syncthreads();
    }

    // epilogue: fragments -> fp32 Y (+bias); for Q,K also bf16 hi/lo planes
    __nv_bfloat16* qh = (z < 2) ? g_qkh[z] : 0;
    __nv_bfloat16* ql = (z < 2) ? g_qkl[z] : 0;
#pragma unroll
    for (int i = 0; i < 4; ++i) {
        int r0 = bm + m0 + i * 16 + (lane >> 2);
#pragma unroll
        for (int j = 0; j < 4; ++j) {
            int col = bn + n0 + j * 8 + (lane & 3) * 2;
            float bx = bias[col], by = bias[col + 1];
#pragma unroll
            for (int hh = 0; hh < 2; ++hh) {
                int rr = r0 + hh * 8;
                float v0 = c[i][j][hh * 2] + bx, v1 = c[i][j][hh * 2 + 1] + by;
                *(float2*)(Y + (size_t)rr * DD + col) = make_float2(v0, v1);
                if (z < 2) {
                    __nv_bfloat16 h0 = __float2bfloat16_rn(v0);
                    __nv_bfloat16 h1 = __float2bfloat16_rn(v1);
                    __nv_bfloat16 l0 = __float2bfloat16_rn(v0 - __bfloat162float(h0));
                    __nv_bfloat16 l1 = __float2bfloat16_rn(v1 - __bfloat162float(h1));
                    *(uint32_t*)(qh + (size_t)rr * DD + col) =
                        ((uint32_t)__bfloat16_as_ushort(h1) << 16) | __bfloat16_as_ushort(h0);
                    *(uint32_t*)(ql + (size_t)rr * DD + col) =
                        ((uint32_t)__bfloat16_as_ushort(l1) << 16) | __bfloat16_as_ushort(l0);
                }
            }
        }
    }
}

// ================= sparsity via cp.async + mma.sync ===========================
// grid (16 qtiles, 16 h, 2 b), 256 thr. Q (128x64) planes resident; K chunks of
// 128 keys 3-stage cp.async; scores folded into per-row max/sum registers.
#define SPQ 18432
#define SPQ_TOT 36864
#define SPK_STG 36864
#define SP_DSMEM (SPQ_TOT + 3*SPK_STG)

__global__ __launch_bounds__(256, 1) void sparsity_mma() {
    extern __shared__ char sm[];
    const uint32_t sb = smem_u32(sm);
    __shared__ float sred[2][128][4];
    const int tid = threadIdx.x, lane = tid & 31, wid = tid >> 5;
    const int b = blockIdx.z, h = blockIdx.y, q0 = blockIdx.x * 128;
    const int m0 = (wid >> 2) * 64, n0 = (wid & 3) * 32;
    const __nv_bfloat16* __restrict__ Qh = g_qkh[0];
    const __nv_bfloat16* __restrict__ Ql = g_qkl[0];
    const __nv_bfloat16* __restrict__ Kh = g_qkh[1];
    const __nv_bfloat16* __restrict__ Kl = g_qkl[1];

    auto issueK = [&](int kt) {
        uint32_t base = sb + SPQ_TOT + (uint32_t)(kt % 3) * SPK_STG;
#pragma unroll
        for (int i = 0; i < 4; ++i) {
            int idx = tid + 256 * i;
            int r = idx >> 3, seg = idx & 7;
            uint32_t doff = (uint32_t)r * 144 + seg * 16;
            size_t src = (size_t)(b * LL + kt * 128 + r) * DD + h * HD + seg * 8;
            cpa16(base + doff, Kh + src);
            cpa16(base + 18432 + doff, Kl + src);
        }
        cpa_commit();
    };

    // Q planes + first K chunk in group 0
    {
#pragma unroll
        for (int i = 0; i < 4; ++i) {
            int idx = tid + 256 * i;
            int r = idx >> 3, seg = idx & 7;
            uint32_t doff = (uint32_t)r * 144 + seg * 16;
            size_t src = (size_t)(b * LL + q0 + r) * DD + h * HD + seg * 8;
            cpa16(sb + doff, Qh + src);
            cpa16(sb + SPQ + doff, Ql + src);
        }
    }
    issueK(0);      // commits group 0 (Q + K0)
    issueK(1);

    float rmax[8], rsum[8];
#pragma unroll
    for (int s = 0; s < 8; ++s) { rmax[s] = -FLT_MAX; rsum[s] = 0.f; }

    const uint32_t arow = (uint32_t)(m0 + (lane & 15)) * 144 + ((lane & 16) ? 16 : 0);
    const uint32_t brow0 = (uint32_t)(n0 + (lane & 15)) * 144 + ((lane & 16) ? 16 : 0);
    const uint32_t brow1 = (uint32_t)(n0 + 16 + (lane & 15)) * 144 + ((lane & 16) ? 16 : 0);

#pragma unroll 1
    for (int kt = 0; kt < 16; ++kt) {
        if (kt + 2 < 16) issueK(kt + 2);
        if (kt <= 13) cpa_wait<2>();
        else if (kt == 14) cpa_wait<1>();
        else cpa_wait<0>();
        __syncthreads();

        const uint32_t K = sb + SPQ_TOT + (uint32_t)(kt % 3) * SPK_STG;
        float c[4][4][4];
#pragma unroll
        for (int i = 0; i < 4; ++i)
#pragma unroll
            for (int j = 0; j < 4; ++j)
#pragma unroll
                for (int k = 0; k < 4; ++k) c[i][j][k] = 0.f;

#pragma unroll
        for (int s = 0; s < 4; ++s) {
            const uint32_t ko = s * 32;
            uint32_t ah[4][4], al[4][4], bh[4][2], bl[4][2];
#pragma unroll
            for (int i = 0; i < 4; ++i) {
                ldsm4(ah[i], sb + arow + i * 2304 + ko);
                ldsm4(al[i], sb + SPQ + arow + i * 2304 + ko);
            }
            {
                uint32_t qr[4];
                ldsm4(qr, K + brow0 + ko);
                bh[0][0] = qr[0]; bh[0][1] = qr[2]; bh[1][0] = qr[1]; bh[1][1] = qr[3];
                ldsm4(qr, K + brow1 + ko);
                bh[2][0] = qr[0]; bh[2][1] = qr[2]; bh[3][0] = qr[1]; bh[3][1] = qr[3];
                ldsm4(qr, K + 18432 + brow0 + ko);
                bl[0][0] = qr[0]; bl[0][1] = qr[2]; bl[1][0] = qr[1]; bl[1][1] = qr[3];
                ldsm4(qr, K + 18432 + brow1 + ko);
                bl[2][0] = qr[0]; bl[2][1] = qr[2]; bl[3][0] = qr[1]; bl[3][1] = qr[3];
            }
#pragma unroll
            for (int i = 0; i < 4; ++i)
#pragma unroll
                for (int j = 0; j < 4; ++j) {
                    mma16816(c[i][j], ah[i], bh[j]);
                    mma16816(c[i][j], ah[i], bl[j]);
                    mma16816(c[i][j], al[i], bh[j]);
                }
        }
#pragma unroll
        for (int i = 0; i < 4; ++i)
#pragma unroll
            for (int hh = 0; hh < 2; ++hh) {
                float m = -FLT_MAX, su = 0.f;
#pragma unroll
                for (int j = 0; j < 4; ++j) {
                    float x = c[i][j][hh * 2], y = c[i][j][hh * 2 + 1];
                    m = fmaxf(m, fmaxf(x, y));
                    su += x + y;
                }
                rmax[i * 2 + hh] = fmaxf(rmax[i * 2 + hh], m);
                rsum[i * 2 + hh] += su;
            }
        __syncthreads();
    }

    // reduce across quad lanes (different n columns, same row)
#pragma unroll
    for (int s = 0; s < 8; ++s) {
        rmax[s] = fmaxf(rmax[s], __shfl_xor_sync(0xffffffffu, rmax[s], 1));
        rmax[s] = fmaxf(rmax[s], __shfl_xor_sync(0xffffffffu, rmax[s], 2));
        rsum[s] += __shfl_xor_sync(0xffffffffu, rsum[s], 1);
        rsum[s] += __shfl_xor_sync(0xffffffffu, rsum[s], 2);
    }
    if ((lane & 3) == 0) {
#pragma unroll
        for (int i = 0; i < 4; ++i)
#pragma unroll
            for (int hh = 0; hh < 2; ++hh) {
                int row = m0 + i * 16 + hh * 8 + (lane >> 2);
                sred[0][row][wid & 3] = rmax[i * 2 + hh];
                sred[1][row][wid & 3] = rsum[i * 2 + hh];
            }
    }
    __syncthreads();
    if (tid < 128) {
        float m = fmaxf(fmaxf(sred[0][tid][0], sred[0][tid][1]),
                        fmaxf(sred[0][tid][2], sred[0][tid][3]));
        float su = sred[1][tid][0] + sred[1][tid][1] + sred[1][tid][2] + sred[1][tid][3];
        g_sp[(b * HH + h) * LL + q0 + tid] = SCALE * m - SCALE * su * (1.0f / (float)LL);
    }
}

// ---------------- clear selection mask ----------------
__global__ void clear_kernel() {
    int i = blockIdx.x * 256 + threadIdx.x;
    if (i < BB * LL) g_selmask[i] = 0u;
}

// ---------------- top-40 per (b,h) ----------------
__global__ __launch_bounds__(256) void topk_kernel() {
    const int bh = blockIdx.x;
    const int b = bh >> 4, h = bh & 15;
    __shared__ float sp[LL];
    __shared__ float rv[8];
    __shared__ int ri[8];
    const int tid = threadIdx.x;
    for (int j = tid; j < LL; j += 256) sp[j] = g_sp[bh * LL + j];
    __syncthreads();
    for (int it = 0; it < TOPU; ++it) {
        float bv = -FLT_MAX; int bi = 1 << 30;
        for (int j = tid; j < LL; j += 256) {
            float v = sp[j];
            if (v > bv || (v == bv && j < bi)) { bv = v; bi = j; }
        }
#pragma unroll
        for (int o = 16; o > 0; o >>= 1) {
            float ov = __shfl_xor_sync(0xffffffffu, bv, o);
            int oi = __shfl_xor_sync(0xffffffffu, bi, o);
            if (ov > bv || (ov == bv && oi < bi)) { bv = ov; bi = oi; }
        }
        if ((tid & 31) == 0) { rv[tid >> 5] = bv; ri[tid >> 5] = bi; }
        __syncthreads();
        if (tid == 0) {
            float mv = -FLT_MAX; int mi = 1 << 30;
            for (int w = 0; w < 8; ++w)
                if (rv[w] > mv || (rv[w] == mv && ri[w] < mi)) { mv = rv[w]; mi = ri[w]; }
            g_topk[bh * TOPU + it] = mi;
            sp[mi] = -FLT_MAX;
            int row = b * LL + mi;
            atomicOr(&g_selmask[row], 1u << h);
            g_selu[row * HH + h] = it;
        }
        __syncthreads();
    }
}

// ---------------- attention over the top queries ----------------
__global__ __launch_bounds__(256) void attn_kernel() {
    const int b = blockIdx.z, h = blockIdx.y, ut = blockIdx.x;
    const int bh = b * HH + h;
    __shared__ float Qs[4][64];
    __shared__ float P[4][LL];
    __shared__ float red[4][8];
    __shared__ float gmx[4], gsm[4];
    __shared__ float cred[8][4][64];
    const float* __restrict__ gq = g_qkv[0];
    const float* __restrict__ gk = g_qkv[1];
    const float* __restrict__ gv = g_qkv[2];
    const int tid = threadIdx.x, lane = tid & 31, wp = tid >> 5;
    {
        int u = tid >> 6, d = tid & 63;
        int qi = g_topk[bh * TOPU + ut * 4 + u];
        Qs[u][d] = gq[((size_t)(b * LL + qi)) * DD + h * HD + d];
    }
    __syncthreads();
    const float* Kb = gk + (size_t)(b * LL) * DD + h * HD;
    float lm[4] = {-FLT_MAX, -FLT_MAX, -FLT_MAX, -FLT_MAX};
#pragma unroll
    for (int j = 0; j < 8; ++j) {
        int k = tid + 256 * j;
        const float4* kr = (const float4*)(Kb + (size_t)k * DD);
        float s[4] = {0.f, 0.f, 0.f, 0.f};
#pragma unroll
        for (int dv = 0; dv < 16; ++dv) {
            float4 kv = kr[dv];
#pragma unroll
            for (int u = 0; u < 4; ++u)
                s[u] += Qs[u][dv * 4 + 0] * kv.x + Qs[u][dv * 4 + 1] * kv.y +
                        Qs[u][dv * 4 + 2] * kv.z + Qs[u][dv * 4 + 3] * kv.w;
        }
#pragma unroll
        for (int u = 0; u < 4; ++u) {
            float sv = s[u] * SCALE;
            P[u][k] = sv;
            lm[u] = fmaxf(lm[u], sv);
        }
    }
#pragma unroll
    for (int u = 0; u < 4; ++u) {
#pragma unroll
        for (int o = 16; o > 0; o >>= 1) lm[u] = fmaxf(lm[u], __shfl_xor_sync(0xffffffffu, lm[u], o));
        if (lane == 0) red[u][wp] = lm[u];
    }
    __syncthreads();
    if (tid < 4) {
        float m = red[tid][0];
        for (int w = 1; w < 8; ++w) m = fmaxf(m, red[tid][w]);
        gmx[tid] = m;
    }
    __syncthreads();
    float ls[4] = {0.f, 0.f, 0.f, 0.f};
#pragma unroll
    for (int j = 0; j < 8; ++j) {
        int k = tid + 256 * j;
#pragma unroll
        for (int u = 0; u < 4; ++u) {
            float e = expf(P[u][k] - gmx[u]);
            P[u][k] = e;
            ls[u] += e;
        }
    }
#pragma unroll
    for (int u = 0; u < 4; ++u) {
#pragma unroll
        for (int o = 16; o > 0; o >>= 1) ls[u] += __shfl_xor_sync(0xffffffffu, ls[u], o);
        if (lane == 0) red[u][wp] = ls[u];
    }
    __syncthreads();
    if (tid < 4) {
        float s = 0.f;
        for (int w = 0; w < 8; ++w) s += red[tid][w];
        gsm[tid] = s;
    }
    __syncthreads();
    const float* Vb = gv + (size_t)(b * LL) * DD + h * HD;
    const int d0 = lane * 2;
    float c[4][2] = {{0.f,0.f},{0.f,0.f},{0.f,0.f},{0.f,0.f}};
    const int k0 = wp * 256;
    for (int kk = 0; kk < 256; ++kk) {
        int k = k0 + kk;
        float2 v = *(const float2*)(Vb + (size_t)k * DD + d0);
#pragma unroll
        for (int u = 0; u < 4; ++u) {
            float p = P[u][k];
            c[u][0] += p * v.x;
            c[u][1] += p * v.y;
        }
    }
#pragma unroll
    for (int u = 0; u < 4; ++u) {
        cred[wp][u][d0] = c[u][0];
        cred[wp][u][d0 + 1] = c[u][1];
    }
    __syncthreads();
    {
        int u = tid >> 6, d = tid & 63;
        float s = 0.f;
#pragma unroll
        for (int w = 0; w < 8; ++w) s += cred[w][u][d];
        g_ctx[((size_t)bh * TOPU + ut * 4 + u) * HD + d] = s / gsm[u];
    }
}

// ---------------- base = mean(V) over sequence ----------------
__global__ void base_kernel() {
    int b = blockIdx.y;
    int c = blockIdx.x * 256 + threadIdx.x;
    const float* p = g_qkv[2] + (size_t)b * LL * DD + c;
    float s = 0.f;
    for (int l = 0; l < LL; ++l) s += p[(size_t)l * DD];
    g_base[b * DD + c] = s * (1.0f / (float)LL);
}

// ---------------- base_out = base_row @ Wo^T + bo ----------------
__global__ __launch_bounds__(256) void baseout_kernel(const float* __restrict__ Wo,
                                                      const float* __restrict__ bo) {
    int b = blockIdx.y;
    int n = blockIdx.x * 256 + threadIdx.x;
    __shared__ float br[DD];
    for (int j = threadIdx.x; j < DD; j += 256) br[j] = g_base[b * DD + j];
    __syncthreads();
    const float4* wr = (const float4*)(Wo + (size_t)n * DD);
    const float4* b4 = (const float4*)br;
    float s = bo[n];
    for (int c = 0; c < DD / 4; ++c) {
        float4 w = wr[c], v = b4[c];
        s += w.x * v.x + w.y * v.y + w.z * v.z + w.w * v.w;
    }
    g_baseout[b * DD + n] = s;
}

// ---------------- final output ----------------
__global__ __launch_bounds__(256) void output_kernel(const float* __restrict__ Wo,
                                                     float* __restrict__ out) {
    const int row = blockIdx.x;
    const int b = row >> 11;
    const int tid = threadIdx.x;
    __shared__ float delta[HD];
    float o[4];
    *(float4*)o = *(const float4*)(g_baseout + b * DD + tid * 4);
    unsigned mask = g_selmask[row];
    while (mask) {
        int h = __ffs(mask) - 1;
        mask &= mask - 1;
        int u = g_selu[row * HH + h];
        if (tid < HD) {
            int bh = b * HH + h;
            delta[tid] = g_ctx[((size_t)bh * TOPU + u) * HD + tid] - g_base[b * DD + h * HD + tid];
        }
        __syncthreads();
        const float* wr = Wo + (size_t)tid * 4 * DD + h * HD;
#pragma unroll
        for (int j = 0; j < 4; ++j) {
            const float4* w4 = (const float4*)(wr + (size_t)j * DD);
            float s = 0.f;
#pragma unroll
            for (int d4 = 0; d4 < HD / 4; ++d4) {
                float4 w = w4[d4];
                s += w.x * delta[d4 * 4 + 0] + w.y * delta[d4 * 4 + 1] +
                     w.z * delta[d4 * 4 + 2] + w.w * delta[d4 * 4 + 3];
            }
            o[j] += s;
        }
        __syncthreads();
    }
    *(float4*)(out + (size_t)row * DD + tid * 4) = make_float4(o[0], o[1], o[2], o[3]);
}

// ---------------- launch ----------------
extern "C" void kernel_launch(void* const* d_in, const int* in_sizes, int n_in,
                              void* d_out, int out_size) {
    const float* query = (const float*)d_in[0];
    const float* key_t = (const float*)d_in[1];
    const float* value = (const float*)d_in[2];
    const float* bq = (const float*)d_in[4];
    const float* bk = (const float*)d_in[6];
    const float* bv = (const float*)d_in[8];
    const float* Wq = (const float*)d_in[3];
    const float* Wk = (const float*)d_in[5];
    const float* Wv = (const float*)d_in[7];
    const float* Wo = (const float*)d_in[9];
    const float* bo = (const float*)d_in[10];
    float* out = (float*)d_out;

    cudaFuncSetAttribute(proj_mma, cudaFuncAttributeMaxDynamicSharedMemorySize, PROJ_DSMEM);
    cudaFuncSetAttribute(sparsity_mma, cudaFuncAttributeMaxDynamicSharedMemorySize, SP_DSMEM);

    split_kernel<<<dim3(4096, 6), 256>>>(query, key_t, value, Wq, Wk, Wv);
    proj_mma<<<dim3(8, 32, 3), 256, PROJ_DSMEM>>>(bq, bk, bv);
    sparsity_mma<<<dim3(LL / 128, HH, BB), 256, SP_DSMEM>>>();
    clear_kernel<<<(BB * LL + 255) / 256, 256>>>();
    topk_kernel<<<BB * HH, 256>>>();
    attn_kernel<<<dim3(TOPU / 4, HH, BB), 256>>>();
    base_kernel<<<dim3(DD / 256, BB), 256>>>();
    baseout_kernel<<<dim3(DD / 256, BB), 256>>>(Wo, bo);
    output_kernel<<<BB * LL, 256>>>(Wo, out);
}

// round 5
// speedup vs baseline: 1.7831x; 1.0092x over previous
#include <cuda_runtime.h>
#include <cuda_bf16.h>
#include <math.h>
#include <float.h>
#include <stdint.h>

// Problem constants
#define BB 2
#define LL 2048
#define DD 1024
#define HH 16
#define HD 64
#define TOPU 40
#define MM (BB*LL)
#define SCALE 0.125f

// ---------------- scratch ----------------
__device__ float g_qkv[3][MM*DD];
__device__ __nv_bfloat16 g_xh[3][MM*DD];
__device__ __nv_bfloat16 g_xl[3][MM*DD];
__device__ __nv_bfloat16 g_wh[3][DD*DD];
__device__ __nv_bfloat16 g_wl[3][DD*DD];
__device__ __nv_bfloat16 g_qkh[2][MM*DD];   // bf16 planes of projected Q,K
__device__ __nv_bfloat16 g_qkl[2][MM*DD];
__device__ float g_sp[BB*HH*LL];
__device__ int g_topk[BB*HH*TOPU];
__device__ unsigned g_selmask[BB*LL];
__device__ int g_selu[BB*LL*HH];
__device__ float g_ctx[BB*HH*TOPU*HD];
__device__ float g_base[BB*DD];
__device__ float g_baseout[BB*DD];

// ---------------- helpers ----------------
__device__ __forceinline__ uint32_t smem_u32(const void* p) {
    uint32_t a;
    asm("{ .reg .u64 t; cvta.to.shared.u64 t, %1; cvt.u32.u64 %0, t; }" : "=r"(a) : "l"(p));
    return a;
}
__device__ __forceinline__ void ldsm4(uint32_t r[4], uint32_t addr) {
    asm volatile("ldmatrix.sync.aligned.m8n8.x4.shared.b16 {%0,%1,%2,%3}, [%4];"
        : "=r"(r[0]), "=r"(r[1]), "=r"(r[2]), "=r"(r[3]) : "r"(addr));
}
__device__ __forceinline__ void mma16816(float c[4], const uint32_t a[4], const uint32_t b[2]) {
    asm volatile("mma.sync.aligned.m16n8k16.row.col.f32.bf16.bf16.f32 "
        "{%0,%1,%2,%3},{%4,%5,%6,%7},{%8,%9},{%0,%1,%2,%3};"
        : "+f"(c[0]), "+f"(c[1]), "+f"(c[2]), "+f"(c[3])
        : "r"(a[0]), "r"(a[1]), "r"(a[2]), "r"(a[3]), "r"(b[0]), "r"(b[1]));
}
__device__ __forceinline__ void cpa16(uint32_t dst, const void* src) {
    asm volatile("cp.async.cg.shared.global [%0], [%1], 16;" :: "r"(dst), "l"(src) : "memory");
}
__device__ __forceinline__ void cpa_commit() {
    asm volatile("cp.async.commit_group;" ::: "memory");
}
template <int N> __device__ __forceinline__ void cpa_wait() {
    asm volatile("cp.async.wait_group %0;" :: "n"(N) : "memory");
}

// fp32x4 -> packed bf16 hi plane + lo plane (2-way split)
__device__ __forceinline__ void split_pack(float4 v, uint2& hi, uint2& lo) {
    __nv_bfloat16 bx = __float2bfloat16_rn(v.x);
    __nv_bfloat16 by = __float2bfloat16_rn(v.y);
    __nv_bfloat16 bz = __float2bfloat16_rn(v.z);
    __nv_bfloat16 bw = __float2bfloat16_rn(v.w);
    hi.x = ((uint32_t)__bfloat16_as_ushort(by) << 16) | __bfloat16_as_ushort(bx);
    hi.y = ((uint32_t)__bfloat16_as_ushort(bw) << 16) | __bfloat16_as_ushort(bz);
    __nv_bfloat16 lx = __float2bfloat16_rn(v.x - __bfloat162float(bx));
    __nv_bfloat16 ly = __float2bfloat16_rn(v.y - __bfloat162float(by));
    __nv_bfloat16 lz = __float2bfloat16_rn(v.z - __bfloat162float(bz));
    __nv_bfloat16 lw = __float2bfloat16_rn(v.w - __bfloat162float(bw));
    lo.x = ((uint32_t)__bfloat16_as_ushort(ly) << 16) | __bfloat16_as_ushort(lx);
    lo.y = ((uint32_t)__bfloat16_as_ushort(lw) << 16) | __bfloat16_as_ushort(lz);
}

// ================= split inputs once: fp32 -> (hi, lo) bf16 planes ===========
__global__ __launch_bounds__(256) void split_kernel(
    const float* __restrict__ q, const float* __restrict__ k, const float* __restrict__ v,
    const float* __restrict__ wq, const float* __restrict__ wk, const float* __restrict__ wv) {
    const int sid = blockIdx.y;
    const float* s;
    __nv_bfloat16 *dh, *dl;
    int n4;
    switch (sid) {
        case 0: s = q;  dh = g_xh[0]; dl = g_xl[0]; n4 = MM * DD / 4; break;
        case 1: s = k;  dh = g_xh[1]; dl = g_xl[1]; n4 = MM * DD / 4; break;
        case 2: s = v;  dh = g_xh[2]; dl = g_xl[2]; n4 = MM * DD / 4; break;
        case 3: s = wq; dh = g_wh[0]; dl = g_wl[0]; n4 = DD * DD / 4; break;
        case 4: s = wk; dh = g_wh[1]; dl = g_wl[1]; n4 = DD * DD / 4; break;
        default: s = wv; dh = g_wh[2]; dl = g_wl[2]; n4 = DD * DD / 4; break;
    }
    int idx = blockIdx.x * 256 + threadIdx.x;
    if (idx >= n4) return;
    float4 val = ((const float4*)s)[idx];
    uint2 hi, lo;
    split_pack(val, hi, lo);
    ((uint2*)dh)[idx] = hi;
    ((uint2*)dl)[idx] = lo;
}

// ================= fused projections via cp.async + mma.sync ==================
// grid (8 ntiles, 32 mtiles, 3), 512 threads (16 warps, warp tile 32x32).
// Tile 128x128, K-chunk 32, 3 stages. Stage: Ah/Al/Bh/Bl, row stride 80B.
#define PROJ_STG 40960
#define PROJ_DSMEM (3*PROJ_STG)

__global__ __launch_bounds__(512, 1) void proj_mma(
    const float* __restrict__ bi0, const float* __restrict__ bi1, const float* __restrict__ bi2) {
    extern __shared__ char sm[];
    const uint32_t sb = smem_u32(sm);
    const int z = blockIdx.z;
    const __nv_bfloat16* __restrict__ Xh = g_xh[z];
    const __nv_bfloat16* __restrict__ Xl = g_xl[z];
    const __nv_bfloat16* __restrict__ Wh = g_wh[z];
    const __nv_bfloat16* __restrict__ Wl = g_wl[z];
    const float* bias = (z == 0) ? bi0 : (z == 1) ? bi1 : bi2;
    float* __restrict__ Y = g_qkv[z];
    const int tid = threadIdx.x, lane = tid & 31, wid = tid >> 5;
    const int bm = blockIdx.y * 128, bn = blockIdx.x * 128;
    const int m0 = (wid >> 2) * 32, n0 = (wid & 3) * 32;

    float c[2][4][4];
#pragma unroll
    for (int i = 0; i < 2; ++i)
#pragma unroll
        for (int j = 0; j < 4; ++j)
#pragma unroll
            for (int k = 0; k < 4; ++k) c[i][j][k] = 0.f;

    auto issue = [&](int kt) {
        uint32_t base = sb + (uint32_t)(kt % 3) * PROJ_STG;
        int r = tid >> 2, seg = tid & 3;
        uint32_t doff = (uint32_t)r * 80 + seg * 16;
        size_t sa = (size_t)(bm + r) * DD + kt * 32 + seg * 8;
        size_t sw = (size_t)(bn + r) * DD + kt * 32 + seg * 8;
        cpa16(base + doff, Xh + sa);
        cpa16(base + 10240 + doff, Xl + sa);
        cpa16(base + 20480 + doff, Wh + sw);
        cpa16(base + 30720 + doff, Wl + sw);
        cpa_commit();
    };

    issue(0); issue(1);

    const uint32_t arow = (uint32_t)(m0 + (lane & 15)) * 80 + ((lane & 16) ? 16 : 0);
    const uint32_t brow0 = (uint32_t)(n0 + (lane & 15)) * 80 + ((lane & 16) ? 16 : 0);
    const uint32_t brow1 = (uint32_t)(n0 + 16 + (lane & 15)) * 80 + ((lane & 16) ? 16 : 0);

#pragma unroll 1
    for (int kt = 0; kt < 32; ++kt) {
        if (kt + 2 < 32) issue(kt + 2);
        if (kt <= 29) cpa_wait<2>();
        else if (kt == 30) cpa_wait<1>();
        else cpa_wait<0>();
        __syncthreads();

        const uint32_t A = sb + (uint32_t)(kt % 3) * PROJ_STG;
#pragma unroll
        for (int s = 0; s < 2; ++s) {
            const uint32_t ko = s * 32;
            uint32_t ah[2][4], al[2][4], bh[4][2], bl[4][2];
#pragma unroll
            for (int i = 0; i < 2; ++i) {
                ldsm4(ah[i], A + arow + i * 1280 + ko);
                ldsm4(al[i], A + 10240 + arow + i * 1280 + ko);
            }
            {
                uint32_t qr[4];
                ldsm4(qr, A + 20480 + brow0 + ko);
                bh[0][0] = qr[0]; bh[0][1] = qr[2]; bh[1][0] = qr[1]; bh[1][1] = qr[3];
                ldsm4(qr, A + 20480 + brow1 + ko);
                bh[2][0] = qr[0]; bh[2][1] = qr[2]; bh[3][0] = qr[1]; bh[3][1] = qr[3];
                ldsm4(qr, A + 30720 + brow0 + ko);
                bl[0][0] = qr[0]; bl[0][1] = qr[2]; bl[1][0] = qr[1]; bl[1][1] = qr[3];
                ldsm4(qr, A + 30720 + brow1 + ko);
                bl[2][0] = qr[0]; bl[2][1] = qr[2]; bl[3][0] = qr[1]; bl[3][1] = qr[3];
            }
#pragma unroll
            for (int i = 0; i < 2; ++i)
#pragma unroll
                for (int j = 0; j < 4; ++j) {
                    mma16816(c[i][j], ah[i], bh[j]);
                    mma16816(c[i][j], ah[i], bl[j]);
                    mma16816(c[i][j], al[i], bh[j]);
                }
        }
        __syncthreads();
    }

    // epilogue: fragments -> fp32 Y (+bias); for Q,K also bf16 hi/lo planes
    __nv_bfloat16* qh = (z < 2) ? g_qkh[z] : 0;
    __nv_bfloat16* ql = (z < 2) ? g_qkl[z] : 0;
#pragma unroll
    for (int i = 0; i < 2; ++i) {
        int r0 = bm + m0 + i * 16 + (lane >> 2);
#pragma unroll
        for (int j = 0; j < 4; ++j) {
            int col = bn + n0 + j * 8 + (lane & 3) * 2;
            float bx = bias[col], by = bias[col + 1];
#pragma unroll
            for (int hh = 0; hh < 2; ++hh) {
                int rr = r0 + hh * 8;
                float v0 = c[i][j][hh * 2] + bx, v1 = c[i][j][hh * 2 + 1] + by;
                *(float2*)(Y + (size_t)rr * DD + col) = make_float2(v0, v1);
                if (z < 2) {
                    __nv_bfloat16 h0 = __float2bfloat16_rn(v0);
                    __nv_bfloat16 h1 = __float2bfloat16_rn(v1);
                    __nv_bfloat16 l0 = __float2bfloat16_rn(v0 - __bfloat162float(h0));
                    __nv_bfloat16 l1 = __float2bfloat16_rn(v1 - __bfloat162float(h1));
                    *(uint32_t*)(qh + (size_t)rr * DD + col) =
                        ((uint32_t)__bfloat16_as_ushort(h1) << 16) | __bfloat16_as_ushort(h0);
                    *(uint32_t*)(ql + (size_t)rr * DD + col) =
                        ((uint32_t)__bfloat16_as_ushort(l1) << 16) | __bfloat16_as_ushort(l0);
                }
            }
        }
    }
}

// ================= sparsity via cp.async + mma.sync ===========================
// grid (16 qtiles, 16 h, 2 b), 512 thr (16 warps, warp tile 32x32).
// Q (128x64) planes resident; K chunks of 128 keys, 3 stages.
#define SPQ 18432
#define SPQ_TOT 36864
#define SPK_STG 36864
#define SP_DSMEM (SPQ_TOT + 3*SPK_STG)

__global__ __launch_bounds__(512, 1) void sparsity_mma() {
    extern __shared__ char sm[];
    const uint32_t sb = smem_u32(sm);
    __shared__ float sred[2][128][4];
    const int tid = threadIdx.x, lane = tid & 31, wid = tid >> 5;
    const int b = blockIdx.z, h = blockIdx.y, q0 = blockIdx.x * 128;
    const int m0 = (wid >> 2) * 32, n0 = (wid & 3) * 32;
    const __nv_bfloat16* __restrict__ Qh = g_qkh[0];
    const __nv_bfloat16* __restrict__ Ql = g_qkl[0];
    const __nv_bfloat16* __restrict__ Kh = g_qkh[1];
    const __nv_bfloat16* __restrict__ Kl = g_qkl[1];

    auto issueK = [&](int kt) {
        uint32_t base = sb + SPQ_TOT + (uint32_t)(kt % 3) * SPK_STG;
#pragma unroll
        for (int i = 0; i < 2; ++i) {
            int idx = tid + 512 * i;
            int r = idx >> 3, seg = idx & 7;
            uint32_t doff = (uint32_t)r * 144 + seg * 16;
            size_t src = (size_t)(b * LL + kt * 128 + r) * DD + h * HD + seg * 8;
            cpa16(base + doff, Kh + src);
            cpa16(base + 18432 + doff, Kl + src);
        }
        cpa_commit();
    };

    // Q planes + first K chunk share group 0
    {
#pragma unroll
        for (int i = 0; i < 2; ++i) {
            int idx = tid + 512 * i;
            int r = idx >> 3, seg = idx & 7;
            uint32_t doff = (uint32_t)r * 144 + seg * 16;
            size_t src = (size_t)(b * LL + q0 + r) * DD + h * HD + seg * 8;
            cpa16(sb + doff, Qh + src);
            cpa16(sb + SPQ + doff, Ql + src);
        }
    }
    issueK(0);
    issueK(1);

    float rmax[4], rsum[4];
#pragma unroll
    for (int s = 0; s < 4; ++s) { rmax[s] = -FLT_MAX; rsum[s] = 0.f; }

    const uint32_t arow = (uint32_t)(m0 + (lane & 15)) * 144 + ((lane & 16) ? 16 : 0);
    const uint32_t brow0 = (uint32_t)(n0 + (lane & 15)) * 144 + ((lane & 16) ? 16 : 0);
    const uint32_t brow1 = (uint32_t)(n0 + 16 + (lane & 15)) * 144 + ((lane & 16) ? 16 : 0);

#pragma unroll 1
    for (int kt = 0; kt < 16; ++kt) {
        if (kt + 2 < 16) issueK(kt + 2);
        if (kt <= 13) cpa_wait<2>();
        else if (kt == 14) cpa_wait<1>();
        else cpa_wait<0>();
        __syncthreads();

        const uint32_t K = sb + SPQ_TOT + (uint32_t)(kt % 3) * SPK_STG;
        float c[2][4][4];
#pragma unroll
        for (int i = 0; i < 2; ++i)
#pragma unroll
            for (int j = 0; j < 4; ++j)
#pragma unroll
                for (int k = 0; k < 4; ++k) c[i][j][k] = 0.f;

#pragma unroll
        for (int s = 0; s < 4; ++s) {
            const uint32_t ko = s * 32;
            uint32_t ah[2][4], al[2][4], bh[4][2], bl[4][2];
#pragma unroll
            for (int i = 0; i < 2; ++i) {
                ldsm4(ah[i], sb + arow + i * 2304 + ko);
                ldsm4(al[i], sb + SPQ + arow + i * 2304 + ko);
            }
            {
                uint32_t qr[4];
                ldsm4(qr, K + brow0 + ko);
                bh[0][0] = qr[0]; bh[0][1] = qr[2]; bh[1][0] = qr[1]; bh[1][1] = qr[3];
                ldsm4(qr, K + brow1 + ko);
                bh[2][0] = qr[0]; bh[2][1] = qr[2]; bh[3][0] = qr[1]; bh[3][1] = qr[3];
                ldsm4(qr, K + 18432 + brow0 + ko);
                bl[0][0] = qr[0]; bl[0][1] = qr[2]; bl[1][0] = qr[1]; bl[1][1] = qr[3];
                ldsm4(qr, K + 18432 + brow1 + ko);
                bl[2][0] = qr[0]; bl[2][1] = qr[2]; bl[3][0] = qr[1]; bl[3][1] = qr[3];
            }
#pragma unroll
            for (int i = 0; i < 2; ++i)
#pragma unroll
                for (int j = 0; j < 4; ++j) {
                    mma16816(c[i][j], ah[i], bh[j]);
                    mma16816(c[i][j], ah[i], bl[j]);
                    mma16816(c[i][j], al[i], bh[j]);
                }
        }
#pragma unroll
        for (int i = 0; i < 2; ++i)
#pragma unroll
            for (int hh = 0; hh < 2; ++hh) {
                float m = -FLT_MAX, su = 0.f;
#pragma unroll
                for (int j = 0; j < 4; ++j) {
                    float x = c[i][j][hh * 2], y = c[i][j][hh * 2 + 1];
                    m = fmaxf(m, fmaxf(x, y));
                    su += x + y;
                }
                rmax[i * 2 + hh] = fmaxf(rmax[i * 2 + hh], m);
                rsum[i * 2 + hh] += su;
            }
        __syncthreads();
    }

    // reduce across quad lanes (different n columns, same row)
#pragma unroll
    for (int s = 0; s < 4; ++s) {
        rmax[s] = fmaxf(rmax[s], __shfl_xor_sync(0xffffffffu, rmax[s], 1));
        rmax[s] = fmaxf(rmax[s], __shfl_xor_sync(0xffffffffu, rmax[s], 2));
        rsum[s] += __shfl_xor_sync(0xffffffffu, rsum[s], 1);
        rsum[s] += __shfl_xor_sync(0xffffffffu, rsum[s], 2);
    }
    if ((lane & 3) == 0) {
#pragma unroll
        for (int i = 0; i < 2; ++i)
#pragma unroll
            for (int hh = 0; hh < 2; ++hh) {
                int row = m0 + i * 16 + hh * 8 + (lane >> 2);
                sred[0][row][wid & 3] = rmax[i * 2 + hh];
                sred[1][row][wid & 3] = rsum[i * 2 + hh];
            }
    }
    __syncthreads();
    if (tid < 128) {
        float m = fmaxf(fmaxf(sred[0][tid][0], sred[0][tid][1]),
                        fmaxf(sred[0][tid][2], sred[0][tid][3]));
        float su = sred[1][tid][0] + sred[1][tid][1] + sred[1][tid][2] + sred[1][tid][3];
        g_sp[(b * HH + h) * LL + q0 + tid] = SCALE * m - SCALE * su * (1.0f / (float)LL);
    }
}

// ---------------- clear selection mask ----------------
__global__ void clear_kernel() {
    int i = blockIdx.x * 256 + threadIdx.x;
    if (i < BB * LL) g_selmask[i] = 0u;
}

// ---------------- top-40 per (b,h) ----------------
__global__ __launch_bounds__(256) void topk_kernel() {
    const int bh = blockIdx.x;
    const int b = bh >> 4, h = bh & 15;
    __shared__ float sp[LL];
    __shared__ float rv[8];
    __shared__ int ri[8];
    const int tid = threadIdx.x;
    for (int j = tid; j < LL; j += 256) sp[j] = g_sp[bh * LL + j];
    __syncthreads();
    for (int it = 0; it < TOPU; ++it) {
        float bv = -FLT_MAX; int bi = 1 << 30;
        for (int j = tid; j < LL; j += 256) {
            float v = sp[j];
            if (v > bv || (v == bv && j < bi)) { bv = v; bi = j; }
        }
#pragma unroll
        for (int o = 16; o > 0; o >>= 1) {
            float ov = __shfl_xor_sync(0xffffffffu, bv, o);
            int oi = __shfl_xor_sync(0xffffffffu, bi, o);
            if (ov > bv || (ov == bv && oi < bi)) { bv = ov; bi = oi; }
        }
        if ((tid & 31) == 0) { rv[tid >> 5] = bv; ri[tid >> 5] = bi; }
        __syncthreads();
        if (tid == 0) {
            float mv = -FLT_MAX; int mi = 1 << 30;
            for (int w = 0; w < 8; ++w)
                if (rv[w] > mv || (rv[w] == mv && ri[w] < mi)) { mv = rv[w]; mi = ri[w]; }
            g_topk[bh * TOPU + it] = mi;
            sp[mi] = -FLT_MAX;
            int row = b * LL + mi;
            atomicOr(&g_selmask[row], 1u << h);
            g_selu[row * HH + h] = it;
        }
        __syncthreads();
    }
}

// ---------------- attention over the top queries ----------------
__global__ __launch_bounds__(256) void attn_kernel() {
    const int b = blockIdx.z, h = blockIdx.y, ut = blockIdx.x;
    const int bh = b * HH + h;
    __shared__ float Qs[4][64];
    __shared__ float P[4][LL];
    __shared__ float red[4][8];
    __shared__ float gmx[4], gsm[4];
    __shared__ float cred[8][4][64];
    const float* __restrict__ gq = g_qkv[0];
    const float* __restrict__ gk = g_qkv[1];
    const float* __restrict__ gv = g_qkv[2];
    const int tid = threadIdx.x, lane = tid & 31, wp = tid >> 5;
    {
        int u = tid >> 6, d = tid & 63;
        int qi = g_topk[bh * TOPU + ut * 4 + u];
        Qs[u][d] = gq[((size_t)(b * LL + qi)) * DD + h * HD + d];
    }
    __syncthreads();
    const float* Kb = gk + (size_t)(b * LL) * DD + h * HD;
    float lm[4] = {-FLT_MAX, -FLT_MAX, -FLT_MAX, -FLT_MAX};
#pragma unroll
    for (int j = 0; j < 8; ++j) {
        int k = tid + 256 * j;
        const float4* kr = (const float4*)(Kb + (size_t)k * DD);
        float s[4] = {0.f, 0.f, 0.f, 0.f};
#pragma unroll
        for (int dv = 0; dv < 16; ++dv) {
            float4 kv = kr[dv];
#pragma unroll
            for (int u = 0; u < 4; ++u)
                s[u] += Qs[u][dv * 4 + 0] * kv.x + Qs[u][dv * 4 + 1] * kv.y +
                        Qs[u][dv * 4 + 2] * kv.z + Qs[u][dv * 4 + 3] * kv.w;
        }
#pragma unroll
        for (int u = 0; u < 4; ++u) {
            float sv = s[u] * SCALE;
            P[u][k] = sv;
            lm[u] = fmaxf(lm[u], sv);
        }
    }
#pragma unroll
    for (int u = 0; u < 4; ++u) {
#pragma unroll
        for (int o = 16; o > 0; o >>= 1) lm[u] = fmaxf(lm[u], __shfl_xor_sync(0xffffffffu, lm[u], o));
        if (lane == 0) red[u][wp] = lm[u];
    }
    __syncthreads();
    if (tid < 4) {
        float m = red[tid][0];
        for (int w = 1; w < 8; ++w) m = fmaxf(m, red[tid][w]);
        gmx[tid] = m;
    }
    __syncthreads();
    float ls[4] = {0.f, 0.f, 0.f, 0.f};
#pragma unroll
    for (int j = 0; j < 8; ++j) {
        int k = tid + 256 * j;
#pragma unroll
        for (int u = 0; u < 4; ++u) {
            float e = expf(P[u][k] - gmx[u]);
            P[u][k] = e;
            ls[u] += e;
        }
    }
#pragma unroll
    for (int u = 0; u < 4; ++u) {
#pragma unroll
        for (int o = 16; o > 0; o >>= 1) ls[u] += __shfl_xor_sync(0xffffffffu, ls[u], o);
        if (lane == 0) red[u][wp] = ls[u];
    }
    __syncthreads();
    if (tid < 4) {
        float s = 0.f;
        for (int w = 0; w < 8; ++w) s += red[tid][w];
        gsm[tid] = s;
    }
    __syncthreads();
    const float* Vb = gv + (size_t)(b * LL) * DD + h * HD;
    const int d0 = lane * 2;
    float c[4][2] = {{0.f,0.f},{0.f,0.f},{0.f,0.f},{0.f,0.f}};
    const int k0 = wp * 256;
    for (int kk = 0; kk < 256; ++kk) {
        int k = k0 + kk;
        float2 v = *(const float2*)(Vb + (size_t)k * DD + d0);
#pragma unroll
        for (int u = 0; u < 4; ++u) {
            float p = P[u][k];
            c[u][0] += p * v.x;
            c[u][1] += p * v.y;
        }
    }
#pragma unroll
    for (int u = 0; u < 4; ++u) {
        cred[wp][u][d0] = c[u][0];
        cred[wp][u][d0 + 1] = c[u][1];
    }
    __syncthreads();
    {
        int u = tid >> 6, d = tid & 63;
        float s = 0.f;
#pragma unroll
        for (int w = 0; w < 8; ++w) s += cred[w][u][d];
        g_ctx[((size_t)bh * TOPU + ut * 4 + u) * HD + d] = s / gsm[u];
    }
}

// ---------------- base = mean(V) over sequence ----------------
__global__ void base_kernel() {
    int b = blockIdx.y;
    int c = blockIdx.x * 256 + threadIdx.x;
    const float* p = g_qkv[2] + (size_t)b * LL * DD + c;
    float s = 0.f;
    for (int l = 0; l < LL; ++l) s += p[(size_t)l * DD];
    g_base[b * DD + c] = s * (1.0f / (float)LL);
}

// ---------------- base_out = base_row @ Wo^T + bo ----------------
__global__ __launch_bounds__(256) void baseout_kernel(const float* __restrict__ Wo,
                                                      const float* __restrict__ bo) {
    int b = blockIdx.y;
    int n = blockIdx.x * 256 + threadIdx.x;
    __shared__ float br[DD];
    for (int j = threadIdx.x; j < DD; j += 256) br[j] = g_base[b * DD + j];
    __syncthreads();
    const float4* wr = (const float4*)(Wo + (size_t)n * DD);
    const float4* b4 = (const float4*)br;
    float s = bo[n];
    for (int c = 0; c < DD / 4; ++c) {
        float4 w = wr[c], v = b4[c];
        s += w.x * v.x + w.y * v.y + w.z * v.z + w.w * v.w;
    }
    g_baseout[b * DD + n] = s;
}

// ---------------- final output ----------------
__global__ __launch_bounds__(256) void output_kernel(const float* __restrict__ Wo,
                                                     float* __restrict__ out) {
    const int row = blockIdx.x;
    const int b = row >> 11;
    const int tid = threadIdx.x;
    __shared__ float delta[HD];
    float o[4];
    *(float4*)o = *(const float4*)(g_baseout + b * DD + tid * 4);
    unsigned mask = g_selmask[row];
    while (mask) {
        int h = __ffs(mask) - 1;
        mask &= mask - 1;
        int u = g_selu[row * HH + h];
        if (tid < HD) {
            int bh = b * HH + h;
            delta[tid] = g_ctx[((size_t)bh * TOPU + u) * HD + tid] - g_base[b * DD + h * HD + tid];
        }
        __syncthreads();
        const float* wr = Wo + (size_t)tid * 4 * DD + h * HD;
#pragma unroll
        for (int j = 0; j < 4; ++j) {
            const float4* w4 = (const float4*)(wr + (size_t)j * DD);
            float s = 0.f;
#pragma unroll
            for (int d4 = 0; d4 < HD / 4; ++d4) {
                float4 w = w4[d4];
                s += w.x * delta[d4 * 4 + 0] + w.y * delta[d4 * 4 + 1] +
                     w.z * delta[d4 * 4 + 2] + w.w * delta[d4 * 4 + 3];
            }
            o[j] += s;
        }
        __syncthreads();
    }
    *(float4*)(out + (size_t)row * DD + tid * 4) = make_float4(o[0], o[1], o[2], o[3]);
}

// ---------------- launch ----------------
extern "C" void kernel_launch(void* const* d_in, const int* in_sizes, int n_in,
                              void* d_out, int out_size) {
    const float* query = (const float*)d_in[0];
    const float* key_t = (const float*)d_in[1];
    const float* value = (const float*)d_in[2];
    const float* bq = (const float*)d_in[4];
    const float* bk = (const float*)d_in[6];
    const float* bv = (const float*)d_in[8];
    const float* Wq = (const float*)d_in[3];
    const float* Wk = (const float*)d_in[5];
    const float* Wv = (const float*)d_in[7];
    const float* Wo = (const float*)d_in[9];
    const float* bo = (const float*)d_in[10];
    float* out = (float*)d_out;

    cudaFuncSetAttribute(proj_mma, cudaFuncAttributeMaxDynamicSharedMemorySize, PROJ_DSMEM);
    cudaFuncSetAttribute(sparsity_mma, cudaFuncAttributeMaxDynamicSharedMemorySize, SP_DSMEM);

    split_kernel<<<dim3(4096, 6), 256>>>(query, key_t, value, Wq, Wk, Wv);
    proj_mma<<<dim3(8, 32, 3), 512, PROJ_DSMEM>>>(bq, bk, bv);
    sparsity_mma<<<dim3(LL / 128, HH, BB), 512, SP_DSMEM>>>();
    clear_kernel<<<(BB * LL + 255) / 256, 256>>>();
    topk_kernel<<<BB * HH, 256>>>();
    attn_kernel<<<dim3(TOPU / 4, HH, BB), 256>>>();
    base_kernel<<<dim3(DD / 256, BB), 256>>>();
    baseout_kernel<<<dim3(DD / 256, BB), 256>>>(Wo, bo);
    output_kernel<<<BB * LL, 256>>>(Wo, out);
}